// round 14
// baseline (speedup 1.0000x reference)
#include <cuda_runtime.h>
#include <cuda_fp16.h>
#include <math.h>
#include <stdint.h>

// ---------------- constants ----------------
#define GHh 45
#define GWw 90
#define NP 4050          // tokens
#define MPAD 4096        // padded token rows
#define EE 768
#define KM 23
#define NFREQ (GHh*KM)   // 1035
#define FPAD 1152        // padded freq rows (9*128)
#define HID 3072
#define PKK 5120
#define HDD 5120
#define NBB 8
#define BSS 96
#define BLK (NBB*BSS*BSS)   // 73728 per layer
#define DHT_SIZE 3110400.0

// ---------------- fp32 scratch ----------------
__device__ __align__(128) float g_A [NP*EE];
__device__ __align__(128) float g_T [2*(size_t)NP*EE];     // inverse C-stage out, 2 split-K partials
__device__ __align__(128) float g_Qr[NFREQ*EE];
__device__ __align__(128) float g_Qi[NFREQ*EE];
__device__ __align__(128) float g_Zr[NFREQ*EE];
__device__ __align__(128) float g_Zi[NFREQ*EE];
__device__ __align__(128) float g_a [2*(size_t)NFREQ*EE];  // fwd C-stage out, 2 split-K partials
__device__ __align__(128) float g_ssum[NP];
__device__ __align__(128) float g_ssq [NP];
// small DFT tables
__device__ __align__(128) float g_WC[GWw*GWw];
__device__ __align__(128) float g_WS[GWw*GWw];
__device__ __align__(128) float g_WCm[GWw*GWw];   // (cos-sin)/SIZE
__device__ __align__(128) float g_WCp[GWw*GWw];   // (cos+sin)/SIZE
__device__ __align__(128) float g_HC[GHh*GHh];
__device__ __align__(128) float g_HS[GHh*GHh];
// per-layer prepped block weights (ALL 12 layers, hoisted)
__device__ __align__(128) float g_W1p[12*BLK], g_W1m[12*BLK];
__device__ __align__(128) float g_W2p[12*BLK], g_W2m[12*BLK];
__device__ __align__(128) float g_W2a[12*BLK], g_W2b[12*BLK];
__device__ __align__(128) float g_bs [12*NBB*BSS];

// ---------------- fp16 buffers (single precision everywhere) ----------------
__device__ __align__(128) __half g_px [(size_t)MPAD*PKK];
__device__ __align__(128) __half g_t  [(size_t)MPAD*EE];
__device__ __align__(128) __half g_hb [(size_t)MPAD*HID];
__device__ __align__(128) __half g_Ah2[(size_t)MPAD*EE];
__device__ __align__(128) __half g_q2 [(size_t)FPAD*2*EE];
__device__ __align__(128) __half g_s  [(size_t)FPAD*EE];
// weights / tables (single fp16)
__device__ __align__(128) __half g_pw [EE*PKK];
__device__ __align__(128) __half g_fB [EE*2*EE];   // fwd C B
__device__ __align__(128) __half g_iB [2*EE*EE];   // inv C B
__device__ __align__(128) __half g_f1 [(size_t)12*HID*EE];
__device__ __align__(128) __half g_f2 [(size_t)12*EE*HID];
__device__ __align__(128) __half g_hw [HDD*EE];

// ---------------- helpers ----------------
__device__ __forceinline__ uint32_t s2u32(const void* p) {
    uint32_t a;
    asm("{ .reg .u64 t; cvta.to.shared.u64 t, %1; cvt.u32.u64 %0, t; }" : "=r"(a) : "l"(p));
    return a;
}
__device__ __forceinline__ void mma_f16(float* c, const uint32_t* a, const uint32_t* b) {
    asm volatile("mma.sync.aligned.m16n8k16.row.col.f32.f16.f16.f32 "
        "{%0,%1,%2,%3}, {%4,%5,%6,%7}, {%8,%9}, {%0,%1,%2,%3};"
        : "+f"(c[0]), "+f"(c[1]), "+f"(c[2]), "+f"(c[3])
        : "r"(a[0]), "r"(a[1]), "r"(a[2]), "r"(a[3]), "r"(b[0]), "r"(b[1]));
}
__device__ __forceinline__ void cpa16(uint32_t dst, const void* src) {
    asm volatile("cp.async.cg.shared.global [%0], [%1], 16;" :: "r"(dst), "l"(src));
}
__device__ __forceinline__ void ldsm4(uint32_t* r, uint32_t addr) {
    asm volatile("ldmatrix.sync.aligned.m8n8.x4.shared.b16 {%0,%1,%2,%3}, [%4];"
        : "=r"(r[0]), "=r"(r[1]), "=r"(r[2]), "=r"(r[3]) : "r"(addr));
}
__device__ __forceinline__ void ln_from_sums(int tok, float& mu, float& ri) {
    float s = g_ssum[tok], q = g_ssq[tok];
    mu = s * (1.0f/768.0f);
    float v = q * (1.0f/768.0f) - mu*mu;
    ri = rsqrtf(v + 1e-5f);
}

// ---------------- table init ----------------
__global__ void tabC() {
    int idx = blockIdx.x*256 + threadIdx.x;
    if (idx >= EE*EE) return;
    int kc = idx / EE, c = idx % EE;
    long long m = ((long long)kc * c) % EE;
    double a = 2.0 * (double)m / (double)EE;
    double cs = cospi(a), sn = sinpi(a);
    g_fB[kc*2*EE + c]      = __float2half((float)(cs - sn));
    g_fB[kc*2*EE + EE + c] = __float2half((float)(cs + sn));
    g_iB[kc*EE + c]        = __float2half((float)cs);
    g_iB[(EE+kc)*EE + c]   = __float2half((float)(-sn));
}
__global__ void tab90() {
    int idx = blockIdx.x*256 + threadIdx.x;
    if (idx >= GWw*GWw) return;
    int a = idx / GWw, b = idx % GWw;
    long long m = ((long long)a * b) % GWw;
    double ang = 2.0 * (double)m / (double)GWw;
    double cs = cospi(ang), sn = sinpi(ang);
    g_WC[idx]  = (float)cs;
    g_WS[idx]  = (float)sn;
    g_WCm[idx] = (float)((cs - sn) / DHT_SIZE);
    g_WCp[idx] = (float)((cs + sn) / DHT_SIZE);
}
__global__ void tab45() {
    int idx = blockIdx.x*256 + threadIdx.x;
    if (idx >= GHh*GHh) return;
    int a = idx / GHh, b = idx % GHh;
    long long m = ((long long)a * b) % GHh;
    double ang = 2.0 * (double)m / (double)GHh;
    g_HC[idx] = (float)cospi(ang);
    g_HS[idx] = (float)sinpi(ang);
}

__global__ void conv_kernel(const float* __restrict__ in, __half* __restrict__ o, int n) {
    int i = blockIdx.x*256 + threadIdx.x;
    if (i >= n) return;
    o[i] = __float2half(in[i]);
}

// ---------------- fp16 mma.sync GEMM, tile 128Mx64N, k-chunk 32, optional split-K ----
// MODE: 0=store fp32 (+split-K via blockIdx.z), 2=bias+GELU->fp16,
//       3=accumulate(+bias) fp32 + LN stats, 4=store+bias+addmat + LN stats,
//       5=accumulate(+bias) fp32 AND emit fp16, 6=head scatter to output image
#define SMSTR 40
#define A_TB (128*SMSTR*2)
#define B_TB (64*SMSTR*2)
#define BUF_B (A_TB + B_TB)

template<int MODE>
__global__ void __launch_bounds__(256, 3)
hgemm(const __half* __restrict__ A, const __half* __restrict__ B,
      float* __restrict__ C, __half* __restrict__ Csh,
      int Mtrue, int N, int K, const float* __restrict__ bias,
      const float* __restrict__ addm, int ld, long zoff)
{
    extern __shared__ __align__(128) char smem[];
    const int t = threadIdx.x, warp = t >> 5, lane = t & 31;
    const int wm = warp >> 1, wn = warp & 1;
    const int bm = blockIdx.y * 128, bn = blockIdx.x * 64;
    const int kz = blockIdx.z;
    const size_t kbase = (size_t)kz * K;
    if (MODE == 0) C += (size_t)kz * zoff;
    const uint32_t sb = s2u32(smem);

    float acc[2][4][4];
    #pragma unroll
    for (int i = 0; i < 2; i++)
        #pragma unroll
        for (int j = 0; j < 4; j++)
            #pragma unroll
            for (int q = 0; q < 4; q++) acc[i][j][q] = 0.f;

    const int arow = t & 127, ahalf = t >> 7;
    const __half* pA = A + (size_t)(bm + arow) * ld + kbase + ahalf * 16;
    const uint32_t aoff = (uint32_t)(arow * SMSTR + ahalf * 16) * 2;
    const int brow = t >> 2, bseg = t & 3;
    const __half* pB = B + (size_t)(bn + brow) * ld + kbase + bseg * 8;
    const uint32_t boff = (uint32_t)(brow * SMSTR + bseg * 8) * 2;

    // precomputed LDSM base addresses (buffer 0); in-loop: + parity*BUF_B
    uint32_t adA[2][2], adB[2][2];
    {
        const int g = lane >> 3, r = lane & 7;
        #pragma unroll
        for (int step = 0; step < 2; step++) {
            const int ks = step * 16;
            const uint32_t a_off = (uint32_t)(((g & 1) * 8 + r) * SMSTR + ks + (g >> 1) * 8) * 2;
            const uint32_t b_off = (uint32_t)(((g >> 1) * 8 + r) * SMSTR + ks + (g & 1) * 8) * 2;
            #pragma unroll
            for (int mt = 0; mt < 2; mt++)
                adA[step][mt] = sb + (uint32_t)((wm*32 + mt*16) * SMSTR) * 2 + a_off;
            #pragma unroll
            for (int j2 = 0; j2 < 2; j2++)
                adB[step][j2] = sb + A_TB + (uint32_t)((wn*32 + j2*16) * SMSTR) * 2 + b_off;
        }
    }

    const int nch = K >> 5;
    auto issue = [&](int ch) {
        const int k0 = ch << 5;
        const uint32_t dst = sb + (uint32_t)(ch & 1) * BUF_B;
        cpa16(dst + aoff,      pA + k0); cpa16(dst + aoff + 16, pA + k0 + 8);
        cpa16(dst + A_TB + boff, pB + k0);
        asm volatile("cp.async.commit_group;" ::: "memory");
    };

    issue(0);
    for (int ch = 0; ch < nch; ch++) {
        const bool more = (ch + 1) < nch;
        if (more) { issue(ch + 1); asm volatile("cp.async.wait_group 1;" ::: "memory"); }
        else      { asm volatile("cp.async.wait_group 0;" ::: "memory"); }
        __syncthreads();

        const uint32_t bsel = (uint32_t)(ch & 1) * BUF_B;

        #pragma unroll
        for (int step = 0; step < 2; step++) {
            uint32_t a_[2][4], b_[4][2];
            #pragma unroll
            for (int mt = 0; mt < 2; mt++)
                ldsm4(a_[mt], adA[step][mt] + bsel);
            #pragma unroll
            for (int j2 = 0; j2 < 2; j2++) {
                uint32_t tmp[4];
                ldsm4(tmp, adB[step][j2] + bsel);
                b_[j2*2][0]=tmp[0]; b_[j2*2][1]=tmp[1]; b_[j2*2+1][0]=tmp[2]; b_[j2*2+1][1]=tmp[3];
            }
            #pragma unroll
            for (int mt = 0; mt < 2; mt++)
                #pragma unroll
                for (int nt = 0; nt < 4; nt++) mma_f16(acc[mt][nt], a_[mt], b_[nt]);
        }
        __syncthreads();
    }

    // epilogue
    float st_s[2][2], st_q[2][2];
    if (MODE == 3 || MODE == 4) {
        #pragma unroll
        for (int i = 0; i < 2; i++)
            #pragma unroll
            for (int j = 0; j < 2; j++) { st_s[i][j] = 0.f; st_q[i][j] = 0.f; }
    }
    #pragma unroll
    for (int mt = 0; mt < 2; mt++) {
        const int r0 = bm + wm*32 + mt*16 + (lane >> 2);
        #pragma unroll
        for (int nt = 0; nt < 4; nt++) {
            const int c0 = bn + wn*32 + nt*8 + (lane & 3)*2;
            float b0 = 0.f, b1 = 0.f;
            if (MODE == 2 || MODE == 3 || MODE == 4 || MODE == 5) { b0 = bias[c0]; b1 = bias[c0+1]; }
            #pragma unroll
            for (int h = 0; h < 2; h++) {
                const int row = r0 + h*8;
                if (row >= Mtrue) continue;
                float v0 = acc[mt][nt][h*2+0] + b0;
                float v1 = acc[mt][nt][h*2+1] + b1;
                if (MODE == 2) {
                    v0 = 0.5f*v0*(1.0f + erff(v0*0.7071067811865475f));
                    v1 = 0.5f*v1*(1.0f + erff(v1*0.7071067811865475f));
                    __half2 hv; hv.x = __float2half(v0); hv.y = __float2half(v1);
                    *(__half2*)&Csh[(size_t)row*N + c0] = hv;
                } else if (MODE == 3) {
                    float2* cp = (float2*)&C[(size_t)row*N + c0];
                    float2 old = *cp;
                    old.x += v0; old.y += v1;
                    *cp = old;
                    st_s[mt][h] += old.x + old.y;
                    st_q[mt][h] += old.x*old.x + old.y*old.y;
                } else if (MODE == 5) {
                    float2* cp = (float2*)&C[(size_t)row*N + c0];
                    float2 old = *cp;
                    old.x += v0; old.y += v1;
                    *cp = old;
                    __half2 hv; hv.x = __float2half(old.x); hv.y = __float2half(old.y);
                    *(__half2*)&Csh[(size_t)row*N + c0] = hv;
                } else if (MODE == 4) {
                    const float2 am = *(const float2*)&addm[(size_t)row*N + c0];
                    float2 fv; fv.x = v0 + am.x; fv.y = v1 + am.y;
                    *(float2*)&C[(size_t)row*N + c0] = fv;
                    st_s[mt][h] += fv.x + fv.y;
                    st_q[mt][h] += fv.x*fv.x + fv.y*fv.y;
                } else if (MODE == 6) {
                    const int gh = row / 90, gw = row % 90;
                    #pragma unroll
                    for (int e = 0; e < 2; e++) {
                        const int n = c0 + e;
                        const int ph = n / 320;
                        const int rem = n - ph*320;
                        const int pw = rem / 20;
                        const int oc = rem - pw*20;
                        C[(size_t)oc*1036800 + (size_t)(gh*16 + ph)*1440 + (gw*16 + pw)]
                            = (e == 0 ? v0 : v1);
                    }
                } else {
                    float2 fv; fv.x = v0; fv.y = v1;
                    *(float2*)&C[(size_t)row*N + c0] = fv;
                }
            }
        }
    }
    if (MODE == 3 || MODE == 4) {
        #pragma unroll
        for (int mt = 0; mt < 2; mt++) {
            #pragma unroll
            for (int h = 0; h < 2; h++) {
                float s = st_s[mt][h], q = st_q[mt][h];
                s += __shfl_xor_sync(0xffffffffu, s, 1);
                q += __shfl_xor_sync(0xffffffffu, q, 1);
                s += __shfl_xor_sync(0xffffffffu, s, 2);
                q += __shfl_xor_sync(0xffffffffu, q, 2);
                const int row = bm + wm*32 + mt*16 + (lane >> 2) + h*8;
                if ((lane & 3) == 0 && row < Mtrue) {
                    atomicAdd(&g_ssum[row], s);
                    atomicAdd(&g_ssq[row],  q);
                }
            }
        }
    }
}

// ---------------- LN2 with fp16 output (MLP half); also zeroes LN1 accumulators --------
__global__ void ln_h(const float* __restrict__ in, __half* __restrict__ oh,
                     const float* __restrict__ w, const float* __restrict__ b)
{
    int tok = blockIdx.x;
    int tid = threadIdx.x;
    const float* row = in + (size_t)tok*EE;
    float x0 = row[tid], x1 = row[tid+256], x2 = row[tid+512];
    float s  = x0+x1+x2;
    float sq = x0*x0 + x1*x1 + x2*x2;
    #pragma unroll
    for (int o = 16; o > 0; o >>= 1) {
        s  += __shfl_down_sync(0xffffffffu, s,  o);
        sq += __shfl_down_sync(0xffffffffu, sq, o);
    }
    __shared__ float ss[8], ssq[8];
    int warp = tid >> 5, lane = tid & 31;
    if (lane == 0) { ss[warp] = s; ssq[warp] = sq; }
    __syncthreads();
    if (tid == 0) {
        float ts = 0.f, tq = 0.f;
        #pragma unroll
        for (int i = 0; i < 8; i++) { ts += ss[i]; tq += ssq[i]; }
        float m = ts * (1.0f/768.0f);
        float v = tq * (1.0f/768.0f) - m*m;
        ss[0] = m; ssq[0] = rsqrtf(v + 1e-5f);
        g_ssum[tok] = 0.f;
        g_ssq[tok]  = 0.f;
    }
    __syncthreads();
    float m = ss[0], inv = ssq[0];
    size_t base = (size_t)tok*EE;
    #pragma unroll
    for (int j = 0; j < 3; j++) {
        int o = tid + j*256;
        float y = (j==0?x0:(j==1?x1:x2));
        y = (y - m)*inv*w[o] + b[o];
        oh[base + o] = __float2half(y);
    }
}

// ---------------- DHT stage kernels (LN fused via sums) ----------------
__global__ void k_wfwd(const float* __restrict__ nw, const float* __restrict__ nb) {
    extern __shared__ float sm[];          // 90*128 + 180
    float* stat = sm + 90*128;
    int c0 = blockIdx.x*128, h = blockIdx.y, tid = threadIdx.x;
    if (tid < 90) {
        float mu, ri;
        ln_from_sums(h*90+tid, mu, ri);
        stat[tid]    = mu;
        stat[90+tid] = ri;
    }
    __syncthreads();
    float wv = nw[c0+tid], bv = nb[c0+tid];
    for (int w = 0; w < 90; w++) {
        float av = g_A[(h*90+w)*EE + c0+tid];
        sm[w*128+tid] = (av - stat[w]) * stat[90+w] * wv + bv;
    }
    __syncthreads();
    for (int kw = 0; kw < 23; kw++) {
        float ar = 0.f, ai = 0.f;
        #pragma unroll 6
        for (int w = 0; w < 90; w++) {
            float v = sm[w*128+tid];
            ar += v * g_WC[kw*90+w];
            ai -= v * g_WS[kw*90+w];
        }
        g_Qr[(h*23+kw)*EE + c0+tid] = ar;
        g_Qi[(h*23+kw)*EE + c0+tid] = ai;
    }
}
__global__ void k_hfwd() {
    extern __shared__ float sm[];
    float* sr = sm; float* si = sm + 45*128;
    int c0 = blockIdx.x*128, kw = blockIdx.y, tid = threadIdx.x;
    for (int h = 0; h < 45; h++) {
        sr[h*128+tid] = g_Qr[(h*23+kw)*EE + c0+tid];
        si[h*128+tid] = g_Qi[(h*23+kw)*EE + c0+tid];
    }
    __syncthreads();
    for (int kh = 0; kh < 45; kh++) {
        float qr = 0.f, qi = 0.f;
        #pragma unroll 5
        for (int h = 0; h < 45; h++) {
            float ch = g_HC[kh*45+h], sh = g_HS[kh*45+h];
            float ur = sr[h*128+tid], ui = si[h*128+tid];
            qr += ur*ch + ui*sh;
            qi += ui*ch - ur*sh;
        }
        size_t row = (size_t)(kh*23+kw) * (2*EE);
        g_q2[row + c0+tid]      = __float2half(qr);
        g_q2[row + EE + c0+tid] = __float2half(qi);
    }
}
__global__ void k_hinv2() {
    extern __shared__ float sm[];
    float* tr = sm; float* ti = sm + 45*128;
    int c0 = blockIdx.x*128, wp = blockIdx.y, tid = threadIdx.x;
    for (int hp = 0; hp < 45; hp++) {
        size_t row = (size_t)(hp*23+wp) * (2*EE);
        tr[hp*128+tid] = g_T[row + c0+tid]      + g_T[(size_t)NP*EE + row + c0+tid];
        ti[hp*128+tid] = g_T[row + EE + c0+tid] + g_T[(size_t)NP*EE + row + EE + c0+tid];
    }
    __syncthreads();
    for (int a = 0; a < 45; a++) {
        float zr = 0.f, zi = 0.f;
        #pragma unroll 5
        for (int hp = 0; hp < 45; hp++) {
            float ch = g_HC[a*45+hp], sh = g_HS[a*45+hp];
            float xr = tr[hp*128+tid], xi = ti[hp*128+tid];
            zr += xr*ch + xi*sh;
            zi += xi*ch - xr*sh;
        }
        g_Zr[(a*23+wp)*EE + c0+tid] = zr;
        g_Zi[(a*23+wp)*EE + c0+tid] = zi;
    }
}
// inverse W-stage: A += y + LN1(A) (normalization recomputed from sums)
__global__ void k_winv2(const float* __restrict__ nw, const float* __restrict__ nb) {
    extern __shared__ float sm[];
    float* zr = sm; float* zi = sm + 23*128;
    int c0 = blockIdx.x*128, a = blockIdx.y, tid = threadIdx.x;
    for (int wp = 0; wp < 23; wp++) {
        zr[wp*128+tid] = g_Zr[(a*23+wp)*EE + c0+tid];
        zi[wp*128+tid] = g_Zi[(a*23+wp)*EE + c0+tid];
    }
    __syncthreads();
    float wv = nw[c0+tid], bv = nb[c0+tid];
    for (int b = 0; b < 90; b++) {
        float y = 0.f;
        #pragma unroll
        for (int wp = 0; wp < 23; wp++) {
            y += zr[wp*128+tid]*g_WCm[b*90+wp] + zi[wp*128+tid]*g_WCp[b*90+wp];
        }
        int tok = a*90 + b;
        size_t idx = (size_t)tok*EE + c0+tid;
        float mu, ri;
        ln_from_sums(tok, mu, ri);
        float av = g_A[idx];
        float tv = (av - mu) * ri * wv + bv;
        g_A[idx] = av + y + tv;
    }
}

// ---------------- misc elementwise ----------------
__global__ void im2col_kernel(const float* __restrict__ x) {
    int idx = blockIdx.x*256 + threadIdx.x;
    if (idx >= NP*PKK) return;
    int p = idx / PKK, k = idx % PKK;
    int c = k >> 8, r = k & 255;
    int ph = r >> 4, pw = r & 15;
    int gh = p / 90, gw = p % 90;
    float v = x[(size_t)c*1036800 + (size_t)(gh*16+ph)*1440 + (gw*16+pw)];
    g_px[(size_t)p*PKK + k] = __float2half(v);
}

// ---------------- block-weight prep, ALL layers hoisted ----------------
__global__ void prep_pm_all(const float* __restrict__ w1, const float* __restrict__ w2) {
    int idx = blockIdx.x*256 + threadIdx.x;
    if (idx >= 12*BLK) return;
    int l = idx / BLK, i = idx % BLK;
    const float* w1l = w1 + (size_t)l*2*BLK;
    const float* w2l = w2 + (size_t)l*2*BLK;
    g_W1p[idx] = 0.5f*(w1l[i] + w1l[BLK+i]);
    g_W1m[idx] = 0.5f*(w1l[i] - w1l[BLK+i]);
    g_W2p[idx] = 0.5f*(w2l[i] + w2l[BLK+i]);
    g_W2m[idx] = 0.5f*(w2l[i] - w2l[BLK+i]);
}
__global__ void prep_ab_all() {
    int idx = blockIdx.x*128 + threadIdx.x;
    if (idx >= 12*BLK) return;
    int l = idx / BLK, rr = idx % BLK;
    int o = rr % 96;
    int i = (rr / 96) % 96;
    int b = rr / 9216;
    const float* P = g_W2p + (size_t)l*BLK + b*9216;
    const float* M = g_W2m + (size_t)l*BLK + b*9216;
    float aa = g_W2p[idx];
    float bb = g_W2m[idx] + g_W2p[idx];
    #pragma unroll 8
    for (int j = 0; j < 96; j++) {
        aa += P[i*96+j] * M[j*96+o];
        bb += M[i*96+j] * M[j*96+o];
    }
    g_W2a[idx] = aa;
    g_W2b[idx] = bb;
}
__global__ void prep_bs_all(const float* __restrict__ b2) {
    int idx = blockIdx.x*128 + threadIdx.x;
    if (idx >= 12*NBB*BSS) return;
    int l = idx / (NBB*BSS), rr = idx % (NBB*BSS);
    int o = rr % 96, b = rr / 96;
    const float* b2l = b2 + (size_t)l*2*NBB*BSS;
    float v = b2l[rr] + b2l[NBB*BSS + rr];
    const float* M = g_W2m + (size_t)l*BLK;
    #pragma unroll 8
    for (int j = 0; j < 96; j++) v += b2l[b*96+j] * M[(b*96+j)*96+o];
    g_bs[idx] = v;
}

// ---------------- fused block mixing (LN-gather + mix1 + mix2 + soft-thresh) ----------------
#define MROWS 45
#define MIXSM ((9216*2 + MROWS*96*2)*4)
__global__ void k_mixf(const float* __restrict__ b1l,
                       const float* __restrict__ nw, const float* __restrict__ nb,
                       int loff, int lbs) {
    extern __shared__ float sm[];
    float* sW1 = sm;
    float* sW2 = sm + 9216;
    float* sX  = sm + 18432;
    float* sY  = sX + MROWS*96;
    int b = blockIdx.x, tile = blockIdx.y;
    int t = threadIdx.x;
    int o = t % 96, rg = t / 96;
    for (int i = t; i < 9216; i += 288) {
        sW1[i] = g_W1p[loff + b*9216+i];
        sW2[i] = g_W1m[loff + b*9216+i];
    }
    int p0 = tile * MROWS;
    float nwv = nw[b*96+o], nbv = nb[b*96+o];
    for (int pp = rg; pp < MROWS; pp += 3) {
        int p = p0 + pp;
        int h = p / 23, w = p % 23;
        int shh = (45 - h) % 45;
        int sww = (90 - w) % 90;
        int tok = shh*90 + sww;
        float mu, ri;
        ln_from_sums(tok, mu, ri);
        float av = g_A[(size_t)tok*EE + b*96 + o];
        sX[pp*96+o] = g_a[(size_t)p*EE + b*96 + o] + g_a[(size_t)NFREQ*EE + (size_t)p*EE + b*96 + o];
        sY[pp*96+o] = (av - mu) * ri * nwv + nbv;
    }
    __syncthreads();
    float bk = b1l[b*96+o], bn = b1l[NBB*BSS + b*96+o];
    float ok_[15], on_[15];
    {
        int c = 0;
        for (int pp = rg; pp < MROWS; pp += 3, c++) {
            float ak = bk, an = bn;
            #pragma unroll 8
            for (int i = 0; i < 96; i++) {
                float xv = sX[pp*96+i], yv = sY[pp*96+i];
                float wp = sW1[i*96+o], wm = sW2[i*96+o];
                ak += xv*wp + yv*wm;
                an += yv*wp + xv*wm;
            }
            ok_[c] = fmaxf(ak, 0.f);
            on_[c] = fmaxf(an, 0.f);
        }
    }
    __syncthreads();
    {
        int c = 0;
        for (int pp = rg; pp < MROWS; pp += 3, c++) {
            sX[pp*96+o] = ok_[c];
            sY[pp*96+o] = on_[c];
        }
    }
    for (int i = t; i < 9216; i += 288) {
        sW1[i] = g_W2a[loff + b*9216+i];
        sW2[i] = g_W2b[loff + b*9216+i];
    }
    __syncthreads();
    float bsv = g_bs[lbs + b*96+o];
    for (int pp = rg; pp < MROWS; pp += 3) {
        float acc = bsv;
        #pragma unroll 8
        for (int i = 0; i < 96; i++) {
            acc += sX[pp*96+i]*sW1[i*96+o] + sY[pp*96+i]*sW2[i*96+o];
        }
        float aab = fabsf(acc) - 0.01f;
        float v = (aab > 0.f) ? copysignf(aab, acc) : 0.f;
        g_s[(size_t)(p0+pp)*EE + b*96 + o] = __float2half(v);
    }
}

// ---------------- host orchestration ----------------
extern "C" void kernel_launch(void* const* d_in, const int* in_sizes, int n_in,
                              void* d_out, int out_size)
{
    const float* x        = (const float*)d_in[0];
    const float* patch_w  = (const float*)d_in[1];
    const float* patch_b  = (const float*)d_in[2];
    const float* pos      = (const float*)d_in[3];
    const float* norm1_w  = (const float*)d_in[4];
    const float* norm1_b  = (const float*)d_in[5];
    const float* w1       = (const float*)d_in[6];
    const float* b1       = (const float*)d_in[7];
    const float* w2       = (const float*)d_in[8];
    const float* b2       = (const float*)d_in[9];
    const float* norm2_w  = (const float*)d_in[10];
    const float* norm2_b  = (const float*)d_in[11];
    const float* fc1_w    = (const float*)d_in[12];
    const float* fc1_b    = (const float*)d_in[13];
    const float* fc2_w    = (const float*)d_in[14];
    const float* fc2_b    = (const float*)d_in[15];
    const float* head_w   = (const float*)d_in[16];
    float* out = (float*)d_out;

    float *pA,*pTT,*pa;
    cudaGetSymbolAddress((void**)&pA,  g_A);
    cudaGetSymbolAddress((void**)&pTT, g_T);
    cudaGetSymbolAddress((void**)&pa,  g_a);

    __half *px,*pt,*phb,*ah2,*q2,*ps;
    __half *pw,*fB,*iB,*f1,*f2,*hw;
    cudaGetSymbolAddress((void**)&px,  g_px);
    cudaGetSymbolAddress((void**)&pt,  g_t);
    cudaGetSymbolAddress((void**)&phb, g_hb);
    cudaGetSymbolAddress((void**)&ah2, g_Ah2);
    cudaGetSymbolAddress((void**)&q2,  g_q2);
    cudaGetSymbolAddress((void**)&ps,  g_s);
    cudaGetSymbolAddress((void**)&pw,  g_pw);
    cudaGetSymbolAddress((void**)&fB,  g_fB);
    cudaGetSymbolAddress((void**)&iB,  g_iB);
    cudaGetSymbolAddress((void**)&f1,  g_f1);
    cudaGetSymbolAddress((void**)&f2,  g_f2);
    cudaGetSymbolAddress((void**)&hw,  g_hw);

    cudaFuncSetAttribute(k_wfwd,  cudaFuncAttributeMaxDynamicSharedMemorySize, 90*128*4 + 180*4);
    cudaFuncSetAttribute(k_hfwd,  cudaFuncAttributeMaxDynamicSharedMemorySize, 2*45*128*4);
    cudaFuncSetAttribute(k_hinv2, cudaFuncAttributeMaxDynamicSharedMemorySize, 2*45*128*4);
    cudaFuncSetAttribute(k_winv2, cudaFuncAttributeMaxDynamicSharedMemorySize, 2*23*128*4);
    cudaFuncSetAttribute(k_mixf,  cudaFuncAttributeMaxDynamicSharedMemorySize, MIXSM);
    cudaFuncSetAttribute(hgemm<0>, cudaFuncAttributeMaxDynamicSharedMemorySize, 2*BUF_B);
    cudaFuncSetAttribute(hgemm<2>, cudaFuncAttributeMaxDynamicSharedMemorySize, 2*BUF_B);
    cudaFuncSetAttribute(hgemm<3>, cudaFuncAttributeMaxDynamicSharedMemorySize, 2*BUF_B);
    cudaFuncSetAttribute(hgemm<4>, cudaFuncAttributeMaxDynamicSharedMemorySize, 2*BUF_B);
    cudaFuncSetAttribute(hgemm<5>, cudaFuncAttributeMaxDynamicSharedMemorySize, 2*BUF_B);
    cudaFuncSetAttribute(hgemm<6>, cudaFuncAttributeMaxDynamicSharedMemorySize, 2*BUF_B);

    // tables + weight converts + ALL-layer block-weight prep (once)
    tabC <<<(EE*EE + 255)/256, 256>>>();
    tab90<<<(GWw*GWw + 255)/256, 256>>>();
    tab45<<<(GHh*GHh + 255)/256, 256>>>();
    conv_kernel<<<(EE*PKK + 255)/256, 256>>>(patch_w, pw, EE*PKK);
    conv_kernel<<<(HDD*EE + 255)/256, 256>>>(head_w, hw, HDD*EE);
    conv_kernel<<<(12*HID*EE + 255)/256, 256>>>(fc1_w, f1, 12*HID*EE);
    conv_kernel<<<(12*EE*HID + 255)/256, 256>>>(fc2_w, f2, 12*EE*HID);
    prep_pm_all<<<(12*BLK + 255)/256, 256>>>(w1, w2);
    prep_ab_all<<<(12*BLK + 127)/128, 128>>>();
    prep_bs_all<<<(12*NBB*BSS + 127)/128, 128>>>(b2);

    const dim3 GB(256);
    const int SMB = 2*BUF_B;

    // patch embed (bias + pos fused; emits LN1 stats for layer 0)
    im2col_kernel<<<(NP*PKK + 255)/256, 256>>>(x);
    hgemm<4><<<dim3(EE/64, MPAD/128), GB, SMB>>>(px, pw, pA, nullptr,
                                                 NP, EE, PKK, patch_b, pos, PKK, 0);

    for (int l = 0; l < 12; l++) {
        // ---- AFNO half ----
        k_wfwd<<<dim3(6, 45), 128, 90*128*4 + 180*4>>>(norm1_w + l*EE, norm1_b + l*EE);
        k_hfwd<<<dim3(6, 23), 128, 2*45*128*4>>>();
        // fwd C-stage GEMM: split-K2 (z=0: Q2r x (cos-sin); z=1: Q2i x (cos+sin))
        hgemm<0><<<dim3(EE/64, FPAD/128, 2), GB, SMB>>>(q2, fB, pa, nullptr,
                                                        NFREQ, EE, EE, nullptr, nullptr,
                                                        2*EE, (long)NFREQ*EE);
        k_mixf<<<dim3(8, 23), 288, MIXSM>>>(b1 + (size_t)l*2*NBB*BSS,
                                            norm1_w + l*EE, norm1_b + l*EE, l*BLK, l*NBB*BSS);
        // inv C-stage GEMM: split-K2 over the 768 c-dimension
        hgemm<0><<<dim3((2*EE)/64, FPAD/128, 2), GB, SMB>>>(ps, iB, pTT, nullptr,
                                                            NFREQ, 2*EE, EE/2, nullptr, nullptr,
                                                            EE, (long)NP*EE);
        k_hinv2<<<dim3(6, 23), 128, 2*45*128*4>>>();
        k_winv2<<<dim3(6, 45), 128, 2*23*128*4>>>(norm1_w + l*EE, norm1_b + l*EE);

        // ---- MLP half ----
        ln_h<<<NP, 256>>>(pA, pt, norm2_w + l*EE, norm2_b + l*EE);
        hgemm<2><<<dim3(HID/64, MPAD/128), GB, SMB>>>(pt, f1 + (size_t)l*HID*EE,
                                                      nullptr, phb, NP, HID, EE, fc1_b + l*HID, nullptr,
                                                      EE, 0);
        if (l < 11) {
            hgemm<3><<<dim3(EE/64, MPAD/128), GB, SMB>>>(phb, f2 + (size_t)l*EE*HID,
                                                         pA, nullptr, NP, EE, HID, fc2_b + l*EE, nullptr,
                                                         HID, 0);
        } else {
            hgemm<5><<<dim3(EE/64, MPAD/128), GB, SMB>>>(phb, f2 + (size_t)l*EE*HID,
                                                         pA, ah2, NP, EE, HID, fc2_b + l*EE, nullptr,
                                                         HID, 0);
        }
    }

    // head: GEMM scatters directly into the output image
    hgemm<6><<<dim3(HDD/64, MPAD/128), GB, SMB>>>(ah2, hw, out, nullptr,
                                                  NP, HDD, EE, nullptr, nullptr, EE, 0);
}

// round 15
// speedup vs baseline: 1.1345x; 1.1345x over previous
#include <cuda_runtime.h>
#include <cuda_fp16.h>
#include <math.h>
#include <stdint.h>

// ---------------- constants ----------------
#define GHh 45
#define GWw 90
#define NP 4050          // tokens
#define MPAD 4096        // padded token rows
#define EE 768
#define KM 23
#define NFREQ (GHh*KM)   // 1035
#define FPAD 1152        // padded freq rows (9*128)
#define HID 3072
#define PKK 5120
#define HDD 5120
#define NBB 8
#define BSS 96
#define BLK (NBB*BSS*BSS)   // 73728 per layer
#define DHT_SIZE 3110400.0

// ---------------- fp32 scratch ----------------
__device__ __align__(128) float g_A [NP*EE];
__device__ __align__(128) float g_T [2*(size_t)NP*EE];     // inverse C-stage out, 2 split-K partials
__device__ __align__(128) float g_Qr[NFREQ*EE];
__device__ __align__(128) float g_Qi[NFREQ*EE];
__device__ __align__(128) float g_Zr[NFREQ*EE];
__device__ __align__(128) float g_Zi[NFREQ*EE];
__device__ __align__(128) float g_a [2*(size_t)NFREQ*EE];  // fwd C-stage out, 2 split-K partials
__device__ __align__(128) float g_ssum[NP];
__device__ __align__(128) float g_ssq [NP];
// small DFT tables
__device__ __align__(128) float g_WC[GWw*GWw];
__device__ __align__(128) float g_WS[GWw*GWw];
__device__ __align__(128) float g_WCm[GWw*GWw];   // (cos-sin)/SIZE
__device__ __align__(128) float g_WCp[GWw*GWw];   // (cos+sin)/SIZE
__device__ __align__(128) float g_HC[GHh*GHh];
__device__ __align__(128) float g_HS[GHh*GHh];
// per-layer prepped block weights (ALL 12 layers, hoisted)
__device__ __align__(128) float g_W1p[12*BLK], g_W1m[12*BLK];
__device__ __align__(128) float g_W2p[12*BLK], g_W2m[12*BLK];
__device__ __align__(128) float g_W2a[12*BLK], g_W2b[12*BLK];
__device__ __align__(128) float g_bs [12*NBB*BSS];

// ---------------- fp16 buffers: activations as hi/lo pairs, weights single ----------------
__device__ __align__(128) __half g_pxh[(size_t)MPAD*PKK], g_pxl[(size_t)MPAD*PKK];
__device__ __align__(128) __half g_th [(size_t)MPAD*EE],  g_tl [(size_t)MPAD*EE];
__device__ __align__(128) __half g_hbh[(size_t)MPAD*HID], g_hbl[(size_t)MPAD*HID];
__device__ __align__(128) __half g_Ah2[(size_t)MPAD*EE],  g_Al2[(size_t)MPAD*EE];
__device__ __align__(128) __half g_q2h[(size_t)FPAD*2*EE], g_q2l[(size_t)FPAD*2*EE];
__device__ __align__(128) __half g_sh [(size_t)FPAD*EE],  g_sl [(size_t)FPAD*EE];
// weights / tables (single fp16)
__device__ __align__(128) __half g_pw [EE*PKK];
__device__ __align__(128) __half g_fB [EE*2*EE];   // fwd C B
__device__ __align__(128) __half g_iB [2*EE*EE];   // inv C B
__device__ __align__(128) __half g_f1 [(size_t)12*HID*EE];
__device__ __align__(128) __half g_f2 [(size_t)12*EE*HID];
__device__ __align__(128) __half g_hw [HDD*EE];

// ---------------- helpers ----------------
__device__ __forceinline__ void hsplit(float x, __half& h, __half& l) {
    h = __float2half(x);
    l = __float2half(x - __half2float(h));
}
__device__ __forceinline__ uint32_t s2u32(const void* p) {
    uint32_t a;
    asm("{ .reg .u64 t; cvta.to.shared.u64 t, %1; cvt.u32.u64 %0, t; }" : "=r"(a) : "l"(p));
    return a;
}
__device__ __forceinline__ void mma_f16(float* c, const uint32_t* a, const uint32_t* b) {
    asm volatile("mma.sync.aligned.m16n8k16.row.col.f32.f16.f16.f32 "
        "{%0,%1,%2,%3}, {%4,%5,%6,%7}, {%8,%9}, {%0,%1,%2,%3};"
        : "+f"(c[0]), "+f"(c[1]), "+f"(c[2]), "+f"(c[3])
        : "r"(a[0]), "r"(a[1]), "r"(a[2]), "r"(a[3]), "r"(b[0]), "r"(b[1]));
}
__device__ __forceinline__ void cpa16(uint32_t dst, const void* src) {
    asm volatile("cp.async.cg.shared.global [%0], [%1], 16;" :: "r"(dst), "l"(src));
}
__device__ __forceinline__ void ldsm4(uint32_t* r, uint32_t addr) {
    asm volatile("ldmatrix.sync.aligned.m8n8.x4.shared.b16 {%0,%1,%2,%3}, [%4];"
        : "=r"(r[0]), "=r"(r[1]), "=r"(r[2]), "=r"(r[3]) : "r"(addr));
}
__device__ __forceinline__ void ln_from_sums(int tok, float& mu, float& ri) {
    float s = g_ssum[tok], q = g_ssq[tok];
    mu = s * (1.0f/768.0f);
    float v = q * (1.0f/768.0f) - mu*mu;
    ri = rsqrtf(v + 1e-5f);
}

// ---------------- table init ----------------
__global__ void tabC() {
    int idx = blockIdx.x*256 + threadIdx.x;
    if (idx >= EE*EE) return;
    int kc = idx / EE, c = idx % EE;
    long long m = ((long long)kc * c) % EE;
    double a = 2.0 * (double)m / (double)EE;
    double cs = cospi(a), sn = sinpi(a);
    g_fB[kc*2*EE + c]      = __float2half((float)(cs - sn));
    g_fB[kc*2*EE + EE + c] = __float2half((float)(cs + sn));
    g_iB[kc*EE + c]        = __float2half((float)cs);
    g_iB[(EE+kc)*EE + c]   = __float2half((float)(-sn));
}
__global__ void tab90() {
    int idx = blockIdx.x*256 + threadIdx.x;
    if (idx >= GWw*GWw) return;
    int a = idx / GWw, b = idx % GWw;
    long long m = ((long long)a * b) % GWw;
    double ang = 2.0 * (double)m / (double)GWw;
    double cs = cospi(ang), sn = sinpi(ang);
    g_WC[idx]  = (float)cs;
    g_WS[idx]  = (float)sn;
    g_WCm[idx] = (float)((cs - sn) / DHT_SIZE);
    g_WCp[idx] = (float)((cs + sn) / DHT_SIZE);
}
__global__ void tab45() {
    int idx = blockIdx.x*256 + threadIdx.x;
    if (idx >= GHh*GHh) return;
    int a = idx / GHh, b = idx % GHh;
    long long m = ((long long)a * b) % GHh;
    double ang = 2.0 * (double)m / (double)GHh;
    g_HC[idx] = (float)cospi(ang);
    g_HS[idx] = (float)sinpi(ang);
}

__global__ void conv_kernel(const float* __restrict__ in, __half* __restrict__ o, int n) {
    int i = blockIdx.x*256 + threadIdx.x;
    if (i >= n) return;
    o[i] = __float2half(in[i]);
}

// ---------------- fp16x2 mma.sync GEMM, tile 128Mx64N, k-chunk 32, optional split-K ----
// A = (Ah + Al) fp16 pair, B single fp16. D = Ah*B + Al*B.
// MODE: 0=store fp32 (+split-K via blockIdx.z), 2=bias+GELU->fp16 pair,
//       3=accumulate(+bias) fp32 + LN stats, 4=store+bias+addmat + LN stats,
//       5=accumulate(+bias) fp32 AND emit fp16 pair, 6=head scatter to output image
#define SMSTR 40
#define A_TB (128*SMSTR*2)
#define B_TB (64*SMSTR*2)
#define BUF_B (2*A_TB + B_TB)

template<int MODE>
__global__ void __launch_bounds__(256, 3)
hgemm(const __half* __restrict__ Ah, const __half* __restrict__ Al,
      const __half* __restrict__ B,
      float* __restrict__ C,
      __half* __restrict__ Csh, __half* __restrict__ Csl,
      int Mtrue, int N, int K, const float* __restrict__ bias,
      const float* __restrict__ addm, int ld, long zoff)
{
    extern __shared__ __align__(128) char smem[];
    const int t = threadIdx.x, warp = t >> 5, lane = t & 31;
    const int wm = warp >> 1, wn = warp & 1;
    const int bm = blockIdx.y * 128, bn = blockIdx.x * 64;
    const int kz = blockIdx.z;
    const size_t kbase = (size_t)kz * K;
    if (MODE == 0) C += (size_t)kz * zoff;
    const uint32_t sb = s2u32(smem);

    float acc[2][4][4];
    #pragma unroll
    for (int i = 0; i < 2; i++)
        #pragma unroll
        for (int j = 0; j < 4; j++)
            #pragma unroll
            for (int q = 0; q < 4; q++) acc[i][j][q] = 0.f;

    const int arow = t & 127, ahalf = t >> 7;
    const __half* pAh = Ah + (size_t)(bm + arow) * ld + kbase + ahalf * 16;
    const __half* pAl = Al + (size_t)(bm + arow) * ld + kbase + ahalf * 16;
    const uint32_t aoff = (uint32_t)(arow * SMSTR + ahalf * 16) * 2;
    const int brow = t >> 2, bseg = t & 3;
    const __half* pB = B + (size_t)(bn + brow) * ld + kbase + bseg * 8;
    const uint32_t boff = (uint32_t)(brow * SMSTR + bseg * 8) * 2;

    // precomputed LDSM base addresses (buffer 0); in-loop: + parity*BUF_B
    uint32_t adA[2][2], adB[2][2];
    {
        const int g = lane >> 3, r = lane & 7;
        #pragma unroll
        for (int step = 0; step < 2; step++) {
            const int ks = step * 16;
            const uint32_t a_off = (uint32_t)(((g & 1) * 8 + r) * SMSTR + ks + (g >> 1) * 8) * 2;
            const uint32_t b_off = (uint32_t)(((g >> 1) * 8 + r) * SMSTR + ks + (g & 1) * 8) * 2;
            #pragma unroll
            for (int mt = 0; mt < 2; mt++)
                adA[step][mt] = sb + (uint32_t)((wm*32 + mt*16) * SMSTR) * 2 + a_off;
            #pragma unroll
            for (int j2 = 0; j2 < 2; j2++)
                adB[step][j2] = sb + 2*A_TB + (uint32_t)((wn*32 + j2*16) * SMSTR) * 2 + b_off;
        }
    }

    const int nch = K >> 5;
    auto issue = [&](int ch) {
        const int k0 = ch << 5;
        const uint32_t dst = sb + (uint32_t)(ch & 1) * BUF_B;
        cpa16(dst + aoff,        pAh + k0); cpa16(dst + aoff + 16,        pAh + k0 + 8);
        cpa16(dst + A_TB + aoff, pAl + k0); cpa16(dst + A_TB + aoff + 16, pAl + k0 + 8);
        cpa16(dst + 2*A_TB + boff, pB + k0);
        asm volatile("cp.async.commit_group;" ::: "memory");
    };

    issue(0);
    for (int ch = 0; ch < nch; ch++) {
        const bool more = (ch + 1) < nch;
        if (more) { issue(ch + 1); asm volatile("cp.async.wait_group 1;" ::: "memory"); }
        else      { asm volatile("cp.async.wait_group 0;" ::: "memory"); }
        __syncthreads();

        const uint32_t bsel = (uint32_t)(ch & 1) * BUF_B;

        #pragma unroll
        for (int step = 0; step < 2; step++) {
            uint32_t ah_[2][4], al_[2][4], bh_[4][2];
            #pragma unroll
            for (int mt = 0; mt < 2; mt++) {
                const uint32_t ad = adA[step][mt] + bsel;
                ldsm4(ah_[mt], ad);
                ldsm4(al_[mt], ad + A_TB);
            }
            #pragma unroll
            for (int j2 = 0; j2 < 2; j2++) {
                const uint32_t bd = adB[step][j2] + bsel;
                uint32_t tmp[4];
                ldsm4(tmp, bd);
                bh_[j2*2][0]=tmp[0]; bh_[j2*2][1]=tmp[1]; bh_[j2*2+1][0]=tmp[2]; bh_[j2*2+1][1]=tmp[3];
            }
            #pragma unroll
            for (int mt = 0; mt < 2; mt++)
                #pragma unroll
                for (int nt = 0; nt < 4; nt++) mma_f16(acc[mt][nt], ah_[mt], bh_[nt]);
            #pragma unroll
            for (int mt = 0; mt < 2; mt++)
                #pragma unroll
                for (int nt = 0; nt < 4; nt++) mma_f16(acc[mt][nt], al_[mt], bh_[nt]);
        }
        __syncthreads();
    }

    // epilogue
    float st_s[2][2], st_q[2][2];
    if (MODE == 3 || MODE == 4) {
        #pragma unroll
        for (int i = 0; i < 2; i++)
            #pragma unroll
            for (int j = 0; j < 2; j++) { st_s[i][j] = 0.f; st_q[i][j] = 0.f; }
    }
    #pragma unroll
    for (int mt = 0; mt < 2; mt++) {
        const int r0 = bm + wm*32 + mt*16 + (lane >> 2);
        #pragma unroll
        for (int nt = 0; nt < 4; nt++) {
            const int c0 = bn + wn*32 + nt*8 + (lane & 3)*2;
            float b0 = 0.f, b1 = 0.f;
            if (MODE == 2 || MODE == 3 || MODE == 4 || MODE == 5) { b0 = bias[c0]; b1 = bias[c0+1]; }
            #pragma unroll
            for (int h = 0; h < 2; h++) {
                const int row = r0 + h*8;
                if (row >= Mtrue) continue;
                float v0 = acc[mt][nt][h*2+0] + b0;
                float v1 = acc[mt][nt][h*2+1] + b1;
                if (MODE == 2) {
                    v0 = 0.5f*v0*(1.0f + erff(v0*0.7071067811865475f));
                    v1 = 0.5f*v1*(1.0f + erff(v1*0.7071067811865475f));
                    __half h0, l0, h1, l1;
                    hsplit(v0, h0, l0); hsplit(v1, h1, l1);
                    __half2 hv; hv.x = h0; hv.y = h1;
                    __half2 lv; lv.x = l0; lv.y = l1;
                    *(__half2*)&Csh[(size_t)row*N + c0] = hv;
                    *(__half2*)&Csl[(size_t)row*N + c0] = lv;
                } else if (MODE == 3) {
                    float2* cp = (float2*)&C[(size_t)row*N + c0];
                    float2 old = *cp;
                    old.x += v0; old.y += v1;
                    *cp = old;
                    st_s[mt][h] += old.x + old.y;
                    st_q[mt][h] += old.x*old.x + old.y*old.y;
                } else if (MODE == 5) {
                    float2* cp = (float2*)&C[(size_t)row*N + c0];
                    float2 old = *cp;
                    old.x += v0; old.y += v1;
                    *cp = old;
                    __half h0, l0, h1, l1;
                    hsplit(old.x, h0, l0); hsplit(old.y, h1, l1);
                    __half2 hv; hv.x = h0; hv.y = h1;
                    __half2 lv; lv.x = l0; lv.y = l1;
                    *(__half2*)&Csh[(size_t)row*N + c0] = hv;
                    *(__half2*)&Csl[(size_t)row*N + c0] = lv;
                } else if (MODE == 4) {
                    const float2 am = *(const float2*)&addm[(size_t)row*N + c0];
                    float2 fv; fv.x = v0 + am.x; fv.y = v1 + am.y;
                    *(float2*)&C[(size_t)row*N + c0] = fv;
                    st_s[mt][h] += fv.x + fv.y;
                    st_q[mt][h] += fv.x*fv.x + fv.y*fv.y;
                } else if (MODE == 6) {
                    const int gh = row / 90, gw = row % 90;
                    #pragma unroll
                    for (int e = 0; e < 2; e++) {
                        const int n = c0 + e;
                        const int ph = n / 320;
                        const int rem = n - ph*320;
                        const int pw = rem / 20;
                        const int oc = rem - pw*20;
                        C[(size_t)oc*1036800 + (size_t)(gh*16 + ph)*1440 + (gw*16 + pw)]
                            = (e == 0 ? v0 : v1);
                    }
                } else {
                    float2 fv; fv.x = v0; fv.y = v1;
                    *(float2*)&C[(size_t)row*N + c0] = fv;
                }
            }
        }
    }
    if (MODE == 3 || MODE == 4) {
        #pragma unroll
        for (int mt = 0; mt < 2; mt++) {
            #pragma unroll
            for (int h = 0; h < 2; h++) {
                float s = st_s[mt][h], q = st_q[mt][h];
                s += __shfl_xor_sync(0xffffffffu, s, 1);
                q += __shfl_xor_sync(0xffffffffu, q, 1);
                s += __shfl_xor_sync(0xffffffffu, s, 2);
                q += __shfl_xor_sync(0xffffffffu, q, 2);
                const int row = bm + wm*32 + mt*16 + (lane >> 2) + h*8;
                if ((lane & 3) == 0 && row < Mtrue) {
                    atomicAdd(&g_ssum[row], s);
                    atomicAdd(&g_ssq[row],  q);
                }
            }
        }
    }
}

// ---------------- LN2 with fp16-pair output (MLP half); also zeroes LN1 accumulators --------
__global__ void ln_h(const float* __restrict__ in,
                     __half* __restrict__ oh, __half* __restrict__ ol,
                     const float* __restrict__ w, const float* __restrict__ b)
{
    int tok = blockIdx.x;
    int tid = threadIdx.x;
    const float* row = in + (size_t)tok*EE;
    float x0 = row[tid], x1 = row[tid+256], x2 = row[tid+512];
    float s  = x0+x1+x2;
    float sq = x0*x0 + x1*x1 + x2*x2;
    #pragma unroll
    for (int o = 16; o > 0; o >>= 1) {
        s  += __shfl_down_sync(0xffffffffu, s,  o);
        sq += __shfl_down_sync(0xffffffffu, sq, o);
    }
    __shared__ float ss[8], ssq[8];
    int warp = tid >> 5, lane = tid & 31;
    if (lane == 0) { ss[warp] = s; ssq[warp] = sq; }
    __syncthreads();
    if (tid == 0) {
        float ts = 0.f, tq = 0.f;
        #pragma unroll
        for (int i = 0; i < 8; i++) { ts += ss[i]; tq += ssq[i]; }
        float m = ts * (1.0f/768.0f);
        float v = tq * (1.0f/768.0f) - m*m;
        ss[0] = m; ssq[0] = rsqrtf(v + 1e-5f);
        g_ssum[tok] = 0.f;
        g_ssq[tok]  = 0.f;
    }
    __syncthreads();
    float m = ss[0], inv = ssq[0];
    size_t base = (size_t)tok*EE;
    #pragma unroll
    for (int j = 0; j < 3; j++) {
        int o = tid + j*256;
        float y = (j==0?x0:(j==1?x1:x2));
        y = (y - m)*inv*w[o] + b[o];
        __half h, l; hsplit(y, h, l);
        oh[base + o] = h; ol[base + o] = l;
    }
}

// ---------------- DHT stage kernels (LN fused via sums) ----------------
__global__ void k_wfwd(const float* __restrict__ nw, const float* __restrict__ nb) {
    extern __shared__ float sm[];          // 90*128 + 180
    float* stat = sm + 90*128;
    int c0 = blockIdx.x*128, h = blockIdx.y, tid = threadIdx.x;
    if (tid < 90) {
        float mu, ri;
        ln_from_sums(h*90+tid, mu, ri);
        stat[tid]    = mu;
        stat[90+tid] = ri;
    }
    __syncthreads();
    float wv = nw[c0+tid], bv = nb[c0+tid];
    for (int w = 0; w < 90; w++) {
        float av = g_A[(h*90+w)*EE + c0+tid];
        sm[w*128+tid] = (av - stat[w]) * stat[90+w] * wv + bv;
    }
    __syncthreads();
    for (int kw = 0; kw < 23; kw++) {
        float ar = 0.f, ai = 0.f;
        #pragma unroll 6
        for (int w = 0; w < 90; w++) {
            float v = sm[w*128+tid];
            ar += v * g_WC[kw*90+w];
            ai -= v * g_WS[kw*90+w];
        }
        g_Qr[(h*23+kw)*EE + c0+tid] = ar;
        g_Qi[(h*23+kw)*EE + c0+tid] = ai;
    }
}
__global__ void k_hfwd() {
    extern __shared__ float sm[];
    float* sr = sm; float* si = sm + 45*128;
    int c0 = blockIdx.x*128, kw = blockIdx.y, tid = threadIdx.x;
    for (int h = 0; h < 45; h++) {
        sr[h*128+tid] = g_Qr[(h*23+kw)*EE + c0+tid];
        si[h*128+tid] = g_Qi[(h*23+kw)*EE + c0+tid];
    }
    __syncthreads();
    for (int kh = 0; kh < 45; kh++) {
        float qr = 0.f, qi = 0.f;
        #pragma unroll 5
        for (int h = 0; h < 45; h++) {
            float ch = g_HC[kh*45+h], sh = g_HS[kh*45+h];
            float ur = sr[h*128+tid], ui = si[h*128+tid];
            qr += ur*ch + ui*sh;
            qi += ui*ch - ur*sh;
        }
        size_t row = (size_t)(kh*23+kw) * (2*EE);
        __half h2, l2;
        hsplit(qr, h2, l2); g_q2h[row + c0+tid] = h2;      g_q2l[row + c0+tid] = l2;
        hsplit(qi, h2, l2); g_q2h[row + EE + c0+tid] = h2; g_q2l[row + EE + c0+tid] = l2;
    }
}
__global__ void k_hinv2() {
    extern __shared__ float sm[];
    float* tr = sm; float* ti = sm + 45*128;
    int c0 = blockIdx.x*128, wp = blockIdx.y, tid = threadIdx.x;
    for (int hp = 0; hp < 45; hp++) {
        size_t row = (size_t)(hp*23+wp) * (2*EE);
        tr[hp*128+tid] = g_T[row + c0+tid]      + g_T[(size_t)NP*EE + row + c0+tid];
        ti[hp*128+tid] = g_T[row + EE + c0+tid] + g_T[(size_t)NP*EE + row + EE + c0+tid];
    }
    __syncthreads();
    for (int a = 0; a < 45; a++) {
        float zr = 0.f, zi = 0.f;
        #pragma unroll 5
        for (int hp = 0; hp < 45; hp++) {
            float ch = g_HC[a*45+hp], sh = g_HS[a*45+hp];
            float xr = tr[hp*128+tid], xi = ti[hp*128+tid];
            zr += xr*ch + xi*sh;
            zi += xi*ch - xr*sh;
        }
        g_Zr[(a*23+wp)*EE + c0+tid] = zr;
        g_Zi[(a*23+wp)*EE + c0+tid] = zi;
    }
}
// inverse W-stage: A += y + LN1(A) (normalization recomputed from sums)
__global__ void k_winv2(const float* __restrict__ nw, const float* __restrict__ nb) {
    extern __shared__ float sm[];
    float* zr = sm; float* zi = sm + 23*128;
    int c0 = blockIdx.x*128, a = blockIdx.y, tid = threadIdx.x;
    for (int wp = 0; wp < 23; wp++) {
        zr[wp*128+tid] = g_Zr[(a*23+wp)*EE + c0+tid];
        zi[wp*128+tid] = g_Zi[(a*23+wp)*EE + c0+tid];
    }
    __syncthreads();
    float wv = nw[c0+tid], bv = nb[c0+tid];
    for (int b = 0; b < 90; b++) {
        float y = 0.f;
        #pragma unroll
        for (int wp = 0; wp < 23; wp++) {
            y += zr[wp*128+tid]*g_WCm[b*90+wp] + zi[wp*128+tid]*g_WCp[b*90+wp];
        }
        int tok = a*90 + b;
        size_t idx = (size_t)tok*EE + c0+tid;
        float mu, ri;
        ln_from_sums(tok, mu, ri);
        float av = g_A[idx];
        float tv = (av - mu) * ri * wv + bv;
        g_A[idx] = av + y + tv;
    }
}

// ---------------- misc elementwise ----------------
__global__ void im2col_kernel(const float* __restrict__ x) {
    int idx = blockIdx.x*256 + threadIdx.x;
    if (idx >= NP*PKK) return;
    int p = idx / PKK, k = idx % PKK;
    int c = k >> 8, r = k & 255;
    int ph = r >> 4, pw = r & 15;
    int gh = p / 90, gw = p % 90;
    float v = x[(size_t)c*1036800 + (size_t)(gh*16+ph)*1440 + (gw*16+pw)];
    __half h, l; hsplit(v, h, l);
    size_t o = (size_t)p*PKK + k;
    g_pxh[o] = h; g_pxl[o] = l;
}

// ---------------- block-weight prep, ALL layers hoisted ----------------
__global__ void prep_pm_all(const float* __restrict__ w1, const float* __restrict__ w2) {
    int idx = blockIdx.x*256 + threadIdx.x;
    if (idx >= 12*BLK) return;
    int l = idx / BLK, i = idx % BLK;
    const float* w1l = w1 + (size_t)l*2*BLK;
    const float* w2l = w2 + (size_t)l*2*BLK;
    g_W1p[idx] = 0.5f*(w1l[i] + w1l[BLK+i]);
    g_W1m[idx] = 0.5f*(w1l[i] - w1l[BLK+i]);
    g_W2p[idx] = 0.5f*(w2l[i] + w2l[BLK+i]);
    g_W2m[idx] = 0.5f*(w2l[i] - w2l[BLK+i]);
}
__global__ void prep_ab_all() {
    int idx = blockIdx.x*128 + threadIdx.x;
    if (idx >= 12*BLK) return;
    int l = idx / BLK, rr = idx % BLK;
    int o = rr % 96;
    int i = (rr / 96) % 96;
    int b = rr / 9216;
    const float* P = g_W2p + (size_t)l*BLK + b*9216;
    const float* M = g_W2m + (size_t)l*BLK + b*9216;
    float aa = g_W2p[idx];
    float bb = g_W2m[idx] + g_W2p[idx];
    #pragma unroll 8
    for (int j = 0; j < 96; j++) {
        aa += P[i*96+j] * M[j*96+o];
        bb += M[i*96+j] * M[j*96+o];
    }
    g_W2a[idx] = aa;
    g_W2b[idx] = bb;
}
__global__ void prep_bs_all(const float* __restrict__ b2) {
    int idx = blockIdx.x*128 + threadIdx.x;
    if (idx >= 12*NBB*BSS) return;
    int l = idx / (NBB*BSS), rr = idx % (NBB*BSS);
    int o = rr % 96, b = rr / 96;
    const float* b2l = b2 + (size_t)l*2*NBB*BSS;
    float v = b2l[rr] + b2l[NBB*BSS + rr];
    const float* M = g_W2m + (size_t)l*BLK;
    #pragma unroll 8
    for (int j = 0; j < 96; j++) v += b2l[b*96+j] * M[(b*96+j)*96+o];
    g_bs[idx] = v;
}

// ---------------- fused block mixing (LN-gather + mix1 + mix2 + soft-thresh + split) ----------------
#define MROWS 45
#define MIXSM ((9216*2 + MROWS*96*2)*4)
__global__ void k_mixf(const float* __restrict__ b1l,
                       const float* __restrict__ nw, const float* __restrict__ nb,
                       int loff, int lbs) {
    extern __shared__ float sm[];
    float* sW1 = sm;
    float* sW2 = sm + 9216;
    float* sX  = sm + 18432;
    float* sY  = sX + MROWS*96;
    int b = blockIdx.x, tile = blockIdx.y;
    int t = threadIdx.x;
    int o = t % 96, rg = t / 96;
    for (int i = t; i < 9216; i += 288) {
        sW1[i] = g_W1p[loff + b*9216+i];
        sW2[i] = g_W1m[loff + b*9216+i];
    }
    int p0 = tile * MROWS;
    float nwv = nw[b*96+o], nbv = nb[b*96+o];
    for (int pp = rg; pp < MROWS; pp += 3) {
        int p = p0 + pp;
        int h = p / 23, w = p % 23;
        int shh = (45 - h) % 45;
        int sww = (90 - w) % 90;
        int tok = shh*90 + sww;
        float mu, ri;
        ln_from_sums(tok, mu, ri);
        float av = g_A[(size_t)tok*EE + b*96 + o];
        sX[pp*96+o] = g_a[(size_t)p*EE + b*96 + o] + g_a[(size_t)NFREQ*EE + (size_t)p*EE + b*96 + o];
        sY[pp*96+o] = (av - mu) * ri * nwv + nbv;
    }
    __syncthreads();
    float bk = b1l[b*96+o], bn = b1l[NBB*BSS + b*96+o];
    float ok_[15], on_[15];
    {
        int c = 0;
        for (int pp = rg; pp < MROWS; pp += 3, c++) {
            float ak = bk, an = bn;
            #pragma unroll 8
            for (int i = 0; i < 96; i++) {
                float xv = sX[pp*96+i], yv = sY[pp*96+i];
                float wp = sW1[i*96+o], wm = sW2[i*96+o];
                ak += xv*wp + yv*wm;
                an += yv*wp + xv*wm;
            }
            ok_[c] = fmaxf(ak, 0.f);
            on_[c] = fmaxf(an, 0.f);
        }
    }
    __syncthreads();
    {
        int c = 0;
        for (int pp = rg; pp < MROWS; pp += 3, c++) {
            sX[pp*96+o] = ok_[c];
            sY[pp*96+o] = on_[c];
        }
    }
    for (int i = t; i < 9216; i += 288) {
        sW1[i] = g_W2a[loff + b*9216+i];
        sW2[i] = g_W2b[loff + b*9216+i];
    }
    __syncthreads();
    float bsv = g_bs[lbs + b*96+o];
    for (int pp = rg; pp < MROWS; pp += 3) {
        float acc = bsv;
        #pragma unroll 8
        for (int i = 0; i < 96; i++) {
            acc += sX[pp*96+i]*sW1[i*96+o] + sY[pp*96+i]*sW2[i*96+o];
        }
        float aab = fabsf(acc) - 0.01f;
        float v = (aab > 0.f) ? copysignf(aab, acc) : 0.f;
        __half h, l; hsplit(v, h, l);
        size_t idx = (size_t)(p0+pp)*EE + b*96 + o;
        g_sh[idx] = h; g_sl[idx] = l;
    }
}

// ---------------- host orchestration ----------------
extern "C" void kernel_launch(void* const* d_in, const int* in_sizes, int n_in,
                              void* d_out, int out_size)
{
    const float* x        = (const float*)d_in[0];
    const float* patch_w  = (const float*)d_in[1];
    const float* patch_b  = (const float*)d_in[2];
    const float* pos      = (const float*)d_in[3];
    const float* norm1_w  = (const float*)d_in[4];
    const float* norm1_b  = (const float*)d_in[5];
    const float* w1       = (const float*)d_in[6];
    const float* b1       = (const float*)d_in[7];
    const float* w2       = (const float*)d_in[8];
    const float* b2       = (const float*)d_in[9];
    const float* norm2_w  = (const float*)d_in[10];
    const float* norm2_b  = (const float*)d_in[11];
    const float* fc1_w    = (const float*)d_in[12];
    const float* fc1_b    = (const float*)d_in[13];
    const float* fc2_w    = (const float*)d_in[14];
    const float* fc2_b    = (const float*)d_in[15];
    const float* head_w   = (const float*)d_in[16];
    float* out = (float*)d_out;

    float *pA,*pTT,*pa;
    cudaGetSymbolAddress((void**)&pA,  g_A);
    cudaGetSymbolAddress((void**)&pTT, g_T);
    cudaGetSymbolAddress((void**)&pa,  g_a);

    __half *pxh,*pxl,*th,*tl,*hbh,*hbl,*ah2,*al2,*q2h,*q2l,*sh,*sl;
    __half *pw,*fB,*iB,*f1,*f2,*hw;
    cudaGetSymbolAddress((void**)&pxh, g_pxh);  cudaGetSymbolAddress((void**)&pxl, g_pxl);
    cudaGetSymbolAddress((void**)&th,  g_th);   cudaGetSymbolAddress((void**)&tl,  g_tl);
    cudaGetSymbolAddress((void**)&hbh, g_hbh);  cudaGetSymbolAddress((void**)&hbl, g_hbl);
    cudaGetSymbolAddress((void**)&ah2, g_Ah2);  cudaGetSymbolAddress((void**)&al2, g_Al2);
    cudaGetSymbolAddress((void**)&q2h, g_q2h);  cudaGetSymbolAddress((void**)&q2l, g_q2l);
    cudaGetSymbolAddress((void**)&sh,  g_sh);   cudaGetSymbolAddress((void**)&sl,  g_sl);
    cudaGetSymbolAddress((void**)&pw,  g_pw);
    cudaGetSymbolAddress((void**)&fB,  g_fB);
    cudaGetSymbolAddress((void**)&iB,  g_iB);
    cudaGetSymbolAddress((void**)&f1,  g_f1);
    cudaGetSymbolAddress((void**)&f2,  g_f2);
    cudaGetSymbolAddress((void**)&hw,  g_hw);

    cudaFuncSetAttribute(k_wfwd,  cudaFuncAttributeMaxDynamicSharedMemorySize, 90*128*4 + 180*4);
    cudaFuncSetAttribute(k_hfwd,  cudaFuncAttributeMaxDynamicSharedMemorySize, 2*45*128*4);
    cudaFuncSetAttribute(k_hinv2, cudaFuncAttributeMaxDynamicSharedMemorySize, 2*45*128*4);
    cudaFuncSetAttribute(k_winv2, cudaFuncAttributeMaxDynamicSharedMemorySize, 2*23*128*4);
    cudaFuncSetAttribute(k_mixf,  cudaFuncAttributeMaxDynamicSharedMemorySize, MIXSM);
    cudaFuncSetAttribute(hgemm<0>, cudaFuncAttributeMaxDynamicSharedMemorySize, 2*BUF_B);
    cudaFuncSetAttribute(hgemm<2>, cudaFuncAttributeMaxDynamicSharedMemorySize, 2*BUF_B);
    cudaFuncSetAttribute(hgemm<3>, cudaFuncAttributeMaxDynamicSharedMemorySize, 2*BUF_B);
    cudaFuncSetAttribute(hgemm<4>, cudaFuncAttributeMaxDynamicSharedMemorySize, 2*BUF_B);
    cudaFuncSetAttribute(hgemm<5>, cudaFuncAttributeMaxDynamicSharedMemorySize, 2*BUF_B);
    cudaFuncSetAttribute(hgemm<6>, cudaFuncAttributeMaxDynamicSharedMemorySize, 2*BUF_B);

    // tables + weight converts + ALL-layer block-weight prep (once)
    tabC <<<(EE*EE + 255)/256, 256>>>();
    tab90<<<(GWw*GWw + 255)/256, 256>>>();
    tab45<<<(GHh*GHh + 255)/256, 256>>>();
    conv_kernel<<<(EE*PKK + 255)/256, 256>>>(patch_w, pw, EE*PKK);
    conv_kernel<<<(HDD*EE + 255)/256, 256>>>(head_w, hw, HDD*EE);
    conv_kernel<<<(12*HID*EE + 255)/256, 256>>>(fc1_w, f1, 12*HID*EE);
    conv_kernel<<<(12*EE*HID + 255)/256, 256>>>(fc2_w, f2, 12*EE*HID);
    prep_pm_all<<<(12*BLK + 255)/256, 256>>>(w1, w2);
    prep_ab_all<<<(12*BLK + 127)/128, 128>>>();
    prep_bs_all<<<(12*NBB*BSS + 127)/128, 128>>>(b2);

    const dim3 GB(256);
    const int SMB = 2*BUF_B;

    // patch embed (bias + pos fused; emits LN1 stats for layer 0)
    im2col_kernel<<<(NP*PKK + 255)/256, 256>>>(x);
    hgemm<4><<<dim3(EE/64, MPAD/128), GB, SMB>>>(pxh, pxl, pw, pA, nullptr, nullptr,
                                                 NP, EE, PKK, patch_b, pos, PKK, 0);

    for (int l = 0; l < 12; l++) {
        // ---- AFNO half ----
        k_wfwd<<<dim3(6, 45), 128, 90*128*4 + 180*4>>>(norm1_w + l*EE, norm1_b + l*EE);
        k_hfwd<<<dim3(6, 23), 128, 2*45*128*4>>>();
        // fwd C-stage GEMM: split-K2 (z=0: Q2r x (cos-sin); z=1: Q2i x (cos+sin))
        hgemm<0><<<dim3(EE/64, FPAD/128, 2), GB, SMB>>>(q2h, q2l, fB, pa, nullptr, nullptr,
                                                        NFREQ, EE, EE, nullptr, nullptr,
                                                        2*EE, (long)NFREQ*EE);
        k_mixf<<<dim3(8, 23), 288, MIXSM>>>(b1 + (size_t)l*2*NBB*BSS,
                                            norm1_w + l*EE, norm1_b + l*EE, l*BLK, l*NBB*BSS);
        // inv C-stage GEMM: split-K2 over the 768 c-dimension
        hgemm<0><<<dim3((2*EE)/64, FPAD/128, 2), GB, SMB>>>(sh, sl, iB, pTT, nullptr, nullptr,
                                                            NFREQ, 2*EE, EE/2, nullptr, nullptr,
                                                            EE, (long)NP*EE);
        k_hinv2<<<dim3(6, 23), 128, 2*45*128*4>>>();
        k_winv2<<<dim3(6, 45), 128, 2*23*128*4>>>(norm1_w + l*EE, norm1_b + l*EE);

        // ---- MLP half ----
        ln_h<<<NP, 256>>>(pA, th, tl, norm2_w + l*EE, norm2_b + l*EE);
        hgemm<2><<<dim3(HID/64, MPAD/128), GB, SMB>>>(th, tl, f1 + (size_t)l*HID*EE,
                                                      nullptr, hbh, hbl, NP, HID, EE, fc1_b + l*HID, nullptr,
                                                      EE, 0);
        if (l < 11) {
            hgemm<3><<<dim3(EE/64, MPAD/128), GB, SMB>>>(hbh, hbl, f2 + (size_t)l*EE*HID,
                                                         pA, nullptr, nullptr, NP, EE, HID, fc2_b + l*EE, nullptr,
                                                         HID, 0);
        } else {
            hgemm<5><<<dim3(EE/64, MPAD/128), GB, SMB>>>(hbh, hbl, f2 + (size_t)l*EE*HID,
                                                         pA, ah2, al2, NP, EE, HID, fc2_b + l*EE, nullptr,
                                                         HID, 0);
        }
    }

    // head: GEMM scatters directly into the output image
    hgemm<6><<<dim3(HDD/64, MPAD/128), GB, SMB>>>(ah2, al2, hw, out, nullptr, nullptr,
                                                  NP, HDD, EE, nullptr, nullptr, EE, 0);
}

// round 16
// speedup vs baseline: 1.1747x; 1.0354x over previous
#include <cuda_runtime.h>
#include <cuda_fp16.h>
#include <math.h>
#include <stdint.h>

// ---------------- constants ----------------
#define GHh 45
#define GWw 90
#define NP 4050          // tokens
#define MPAD 4096        // padded token rows
#define EE 768
#define KM 23
#define NFREQ (GHh*KM)   // 1035
#define FPAD 1152        // padded freq rows (9*128)
#define HID 3072
#define PKK 5120
#define HDD 5120
#define NBB 8
#define BSS 96
#define BLK (NBB*BSS*BSS)   // 73728 per layer
#define DHT_SIZE 3110400.0

// ---------------- fp32 scratch ----------------
__device__ __align__(128) float g_A [NP*EE];
__device__ __align__(128) float g_T [2*(size_t)NP*EE];     // inverse C-stage out, 2 split-K partials
__device__ __align__(128) float g_Qr[NFREQ*EE];
__device__ __align__(128) float g_Qi[NFREQ*EE];
__device__ __align__(128) float g_Zr[NFREQ*EE];
__device__ __align__(128) float g_Zi[NFREQ*EE];
__device__ __align__(128) float g_a [2*(size_t)NFREQ*EE];  // fwd C-stage out, 2 split-K partials
__device__ __align__(128) float g_ssum[NP];
__device__ __align__(128) float g_ssq [NP];
// small DFT tables
__device__ __align__(128) float g_WC[GWw*GWw];
__device__ __align__(128) float g_WS[GWw*GWw];
__device__ __align__(128) float g_WCm[GWw*GWw];   // (cos-sin)/SIZE
__device__ __align__(128) float g_WCp[GWw*GWw];   // (cos+sin)/SIZE
__device__ __align__(128) float g_HC[GHh*GHh];
__device__ __align__(128) float g_HS[GHh*GHh];
// per-layer prepped block weights (ALL 12 layers, hoisted)
__device__ __align__(128) float g_W1p[12*BLK], g_W1m[12*BLK];
__device__ __align__(128) float g_W2p[12*BLK], g_W2m[12*BLK];
__device__ __align__(128) float g_W2a[12*BLK], g_W2b[12*BLK];
__device__ __align__(128) float g_bs [12*NBB*BSS];

// ---------------- fp16 buffers: activations as hi/lo pairs, weights single ----------------
__device__ __align__(128) __half g_pxh[(size_t)MPAD*PKK], g_pxl[(size_t)MPAD*PKK];
__device__ __align__(128) __half g_th [(size_t)MPAD*EE],  g_tl [(size_t)MPAD*EE];
__device__ __align__(128) __half g_hbh[(size_t)MPAD*HID], g_hbl[(size_t)MPAD*HID];
__device__ __align__(128) __half g_Ah2[(size_t)MPAD*EE],  g_Al2[(size_t)MPAD*EE];
__device__ __align__(128) __half g_q2h[(size_t)FPAD*2*EE], g_q2l[(size_t)FPAD*2*EE];
__device__ __align__(128) __half g_sh [(size_t)FPAD*EE],  g_sl [(size_t)FPAD*EE];
// weights / tables (single fp16)
__device__ __align__(128) __half g_pw [EE*PKK];
__device__ __align__(128) __half g_fB [EE*2*EE];   // fwd C B
__device__ __align__(128) __half g_iB [2*EE*EE];   // inv C B
__device__ __align__(128) __half g_f1 [(size_t)12*HID*EE];
__device__ __align__(128) __half g_f2 [(size_t)12*EE*HID];
__device__ __align__(128) __half g_hw [HDD*EE];

// ---------------- helpers ----------------
__device__ __forceinline__ void hsplit(float x, __half& h, __half& l) {
    h = __float2half(x);
    l = __float2half(x - __half2float(h));
}
__device__ __forceinline__ uint32_t s2u32(const void* p) {
    uint32_t a;
    asm("{ .reg .u64 t; cvta.to.shared.u64 t, %1; cvt.u32.u64 %0, t; }" : "=r"(a) : "l"(p));
    return a;
}
__device__ __forceinline__ void mma_f16(float* c, const uint32_t* a, const uint32_t* b) {
    asm volatile("mma.sync.aligned.m16n8k16.row.col.f32.f16.f16.f32 "
        "{%0,%1,%2,%3}, {%4,%5,%6,%7}, {%8,%9}, {%0,%1,%2,%3};"
        : "+f"(c[0]), "+f"(c[1]), "+f"(c[2]), "+f"(c[3])
        : "r"(a[0]), "r"(a[1]), "r"(a[2]), "r"(a[3]), "r"(b[0]), "r"(b[1]));
}
__device__ __forceinline__ void cpa16(uint32_t dst, const void* src) {
    asm volatile("cp.async.cg.shared.global [%0], [%1], 16;" :: "r"(dst), "l"(src));
}
__device__ __forceinline__ void ldsm4(uint32_t* r, uint32_t addr) {
    asm volatile("ldmatrix.sync.aligned.m8n8.x4.shared.b16 {%0,%1,%2,%3}, [%4];"
        : "=r"(r[0]), "=r"(r[1]), "=r"(r[2]), "=r"(r[3]) : "r"(addr));
}
__device__ __forceinline__ void ln_from_sums(int tok, float& mu, float& ri) {
    float s = g_ssum[tok], q = g_ssq[tok];
    mu = s * (1.0f/768.0f);
    float v = q * (1.0f/768.0f) - mu*mu;
    ri = rsqrtf(v + 1e-5f);
}

// ---------------- table init ----------------
__global__ void tabC() {
    int idx = blockIdx.x*256 + threadIdx.x;
    if (idx >= EE*EE) return;
    int kc = idx / EE, c = idx % EE;
    long long m = ((long long)kc * c) % EE;
    double a = 2.0 * (double)m / (double)EE;
    double cs = cospi(a), sn = sinpi(a);
    g_fB[kc*2*EE + c]      = __float2half((float)(cs - sn));
    g_fB[kc*2*EE + EE + c] = __float2half((float)(cs + sn));
    g_iB[kc*EE + c]        = __float2half((float)cs);
    g_iB[(EE+kc)*EE + c]   = __float2half((float)(-sn));
}
__global__ void tab90() {
    int idx = blockIdx.x*256 + threadIdx.x;
    if (idx >= GWw*GWw) return;
    int a = idx / GWw, b = idx % GWw;
    long long m = ((long long)a * b) % GWw;
    double ang = 2.0 * (double)m / (double)GWw;
    double cs = cospi(ang), sn = sinpi(ang);
    g_WC[idx]  = (float)cs;
    g_WS[idx]  = (float)sn;
    g_WCm[idx] = (float)((cs - sn) / DHT_SIZE);
    g_WCp[idx] = (float)((cs + sn) / DHT_SIZE);
}
__global__ void tab45() {
    int idx = blockIdx.x*256 + threadIdx.x;
    if (idx >= GHh*GHh) return;
    int a = idx / GHh, b = idx % GHh;
    long long m = ((long long)a * b) % GHh;
    double ang = 2.0 * (double)m / (double)GHh;
    g_HC[idx] = (float)cospi(ang);
    g_HS[idx] = (float)sinpi(ang);
}

__global__ void conv_kernel(const float* __restrict__ in, __half* __restrict__ o, int n) {
    int i = blockIdx.x*256 + threadIdx.x;
    if (i >= n) return;
    o[i] = __float2half(in[i]);
}

// ---------------- fp16x2 mma.sync GEMM, tile 128M x NT(64|128), k-chunk 32, split-K ----
// A = (Ah + Al) fp16 pair, B single fp16. D = Ah*B + Al*B.
// MODE: 0=store fp32 (+split-K via blockIdx.z), 2=bias+GELU->fp16 pair,
//       3=accumulate(+bias) fp32 + LN stats, 4=store+bias+addmat + LN stats,
//       5=accumulate(+bias) fp32 AND emit fp16 pair, 6=head scatter to output image
#define SMSTR 40
#define A_TB (128*SMSTR*2)

template<int MODE, int NT = 64>
__global__ void __launch_bounds__(256, (NT == 64) ? 3 : 2)
hgemm(const __half* __restrict__ Ah, const __half* __restrict__ Al,
      const __half* __restrict__ B,
      float* __restrict__ C,
      __half* __restrict__ Csh, __half* __restrict__ Csl,
      int Mtrue, int N, int K, const float* __restrict__ bias,
      const float* __restrict__ addm, int ld, long zoff)
{
    constexpr int B_TBX = NT*SMSTR*2;
    constexpr int BUFB  = 2*A_TB + B_TBX;
    constexpr int WNT   = NT/16;        // n-subtiles per warp (warp covers NT/2)
    constexpr int NJ    = WNT/2;        // ldsm.x4 loads for B per step

    extern __shared__ __align__(128) char smem[];
    const int t = threadIdx.x, warp = t >> 5, lane = t & 31;
    const int wm = warp >> 1, wn = warp & 1;
    const int bm = blockIdx.y * 128, bn = blockIdx.x * NT;
    const int kz = blockIdx.z;
    const size_t kbase = (size_t)kz * K;
    if (MODE == 0) C += (size_t)kz * zoff;
    const uint32_t sb = s2u32(smem);

    float acc[2][WNT][4];
    #pragma unroll
    for (int i = 0; i < 2; i++)
        #pragma unroll
        for (int j = 0; j < WNT; j++)
            #pragma unroll
            for (int q = 0; q < 4; q++) acc[i][j][q] = 0.f;

    const int arow = t & 127, ahalf = t >> 7;
    const __half* pAh = Ah + (size_t)(bm + arow) * ld + kbase + ahalf * 16;
    const __half* pAl = Al + (size_t)(bm + arow) * ld + kbase + ahalf * 16;
    const uint32_t aoff = (uint32_t)(arow * SMSTR + ahalf * 16) * 2;
    // B loader
    const __half* pB;
    uint32_t boff;
    if (NT == 64) {
        const int brow = t >> 2, bseg = t & 3;
        pB = B + (size_t)(bn + brow) * ld + kbase + bseg * 8;
        boff = (uint32_t)(brow * SMSTR + bseg * 8) * 2;
    } else {
        const int brow = t & 127, bhalf = t >> 7;
        pB = B + (size_t)(bn + brow) * ld + kbase + bhalf * 16;
        boff = (uint32_t)(brow * SMSTR + bhalf * 16) * 2;
    }

    // precomputed LDSM base addresses (buffer 0); in-loop: + parity*BUFB
    uint32_t adA[2][2], adB[2][NJ];
    {
        const int g = lane >> 3, r = lane & 7;
        #pragma unroll
        for (int step = 0; step < 2; step++) {
            const int ks = step * 16;
            const uint32_t a_off = (uint32_t)(((g & 1) * 8 + r) * SMSTR + ks + (g >> 1) * 8) * 2;
            const uint32_t b_off = (uint32_t)(((g >> 1) * 8 + r) * SMSTR + ks + (g & 1) * 8) * 2;
            #pragma unroll
            for (int mt = 0; mt < 2; mt++)
                adA[step][mt] = sb + (uint32_t)((wm*32 + mt*16) * SMSTR) * 2 + a_off;
            #pragma unroll
            for (int j2 = 0; j2 < NJ; j2++)
                adB[step][j2] = sb + 2*A_TB + (uint32_t)((wn*(NT/2) + j2*16) * SMSTR) * 2 + b_off;
        }
    }

    const int nch = K >> 5;
    auto issue = [&](int ch) {
        const int k0 = ch << 5;
        const uint32_t dst = sb + (uint32_t)(ch & 1) * BUFB;
        cpa16(dst + aoff,        pAh + k0); cpa16(dst + aoff + 16,        pAh + k0 + 8);
        cpa16(dst + A_TB + aoff, pAl + k0); cpa16(dst + A_TB + aoff + 16, pAl + k0 + 8);
        if (NT == 64) {
            cpa16(dst + 2*A_TB + boff, pB + k0);
        } else {
            cpa16(dst + 2*A_TB + boff,      pB + k0);
            cpa16(dst + 2*A_TB + boff + 16, pB + k0 + 8);
        }
        asm volatile("cp.async.commit_group;" ::: "memory");
    };

    issue(0);
    for (int ch = 0; ch < nch; ch++) {
        const bool more = (ch + 1) < nch;
        if (more) { issue(ch + 1); asm volatile("cp.async.wait_group 1;" ::: "memory"); }
        else      { asm volatile("cp.async.wait_group 0;" ::: "memory"); }
        __syncthreads();

        const uint32_t bsel = (uint32_t)(ch & 1) * BUFB;

        #pragma unroll
        for (int step = 0; step < 2; step++) {
            uint32_t b_[WNT][2];
            #pragma unroll
            for (int j2 = 0; j2 < NJ; j2++) {
                uint32_t tmp[4];
                ldsm4(tmp, adB[step][j2] + bsel);
                b_[j2*2][0]=tmp[0]; b_[j2*2][1]=tmp[1]; b_[j2*2+1][0]=tmp[2]; b_[j2*2+1][1]=tmp[3];
            }
            #pragma unroll
            for (int mt = 0; mt < 2; mt++) {
                const uint32_t ad = adA[step][mt] + bsel;
                uint32_t ah_[4], al_[4];
                ldsm4(ah_, ad);
                ldsm4(al_, ad + A_TB);
                #pragma unroll
                for (int nt = 0; nt < WNT; nt++) mma_f16(acc[mt][nt], ah_, b_[nt]);
                #pragma unroll
                for (int nt = 0; nt < WNT; nt++) mma_f16(acc[mt][nt], al_, b_[nt]);
            }
        }
        __syncthreads();
    }

    // epilogue
    float st_s[2][2], st_q[2][2];
    if (MODE == 3 || MODE == 4) {
        #pragma unroll
        for (int i = 0; i < 2; i++)
            #pragma unroll
            for (int j = 0; j < 2; j++) { st_s[i][j] = 0.f; st_q[i][j] = 0.f; }
    }
    #pragma unroll
    for (int mt = 0; mt < 2; mt++) {
        const int r0 = bm + wm*32 + mt*16 + (lane >> 2);
        #pragma unroll
        for (int nt = 0; nt < WNT; nt++) {
            const int c0 = bn + wn*(NT/2) + nt*8 + (lane & 3)*2;
            float b0 = 0.f, b1 = 0.f;
            if (MODE == 2 || MODE == 3 || MODE == 4 || MODE == 5) { b0 = bias[c0]; b1 = bias[c0+1]; }
            #pragma unroll
            for (int h = 0; h < 2; h++) {
                const int row = r0 + h*8;
                if (row >= Mtrue) continue;
                float v0 = acc[mt][nt][h*2+0] + b0;
                float v1 = acc[mt][nt][h*2+1] + b1;
                if (MODE == 2) {
                    v0 = 0.5f*v0*(1.0f + erff(v0*0.7071067811865475f));
                    v1 = 0.5f*v1*(1.0f + erff(v1*0.7071067811865475f));
                    __half h0, l0, h1, l1;
                    hsplit(v0, h0, l0); hsplit(v1, h1, l1);
                    __half2 hv; hv.x = h0; hv.y = h1;
                    __half2 lv; lv.x = l0; lv.y = l1;
                    *(__half2*)&Csh[(size_t)row*N + c0] = hv;
                    *(__half2*)&Csl[(size_t)row*N + c0] = lv;
                } else if (MODE == 3) {
                    float2* cp = (float2*)&C[(size_t)row*N + c0];
                    float2 old = *cp;
                    old.x += v0; old.y += v1;
                    *cp = old;
                    st_s[mt][h] += old.x + old.y;
                    st_q[mt][h] += old.x*old.x + old.y*old.y;
                } else if (MODE == 5) {
                    float2* cp = (float2*)&C[(size_t)row*N + c0];
                    float2 old = *cp;
                    old.x += v0; old.y += v1;
                    *cp = old;
                    __half h0, l0, h1, l1;
                    hsplit(old.x, h0, l0); hsplit(old.y, h1, l1);
                    __half2 hv; hv.x = h0; hv.y = h1;
                    __half2 lv; lv.x = l0; lv.y = l1;
                    *(__half2*)&Csh[(size_t)row*N + c0] = hv;
                    *(__half2*)&Csl[(size_t)row*N + c0] = lv;
                } else if (MODE == 4) {
                    const float2 am = *(const float2*)&addm[(size_t)row*N + c0];
                    float2 fv; fv.x = v0 + am.x; fv.y = v1 + am.y;
                    *(float2*)&C[(size_t)row*N + c0] = fv;
                    st_s[mt][h] += fv.x + fv.y;
                    st_q[mt][h] += fv.x*fv.x + fv.y*fv.y;
                } else if (MODE == 6) {
                    const int gh = row / 90, gw = row % 90;
                    #pragma unroll
                    for (int e = 0; e < 2; e++) {
                        const int n = c0 + e;
                        const int ph = n / 320;
                        const int rem = n - ph*320;
                        const int pw = rem / 20;
                        const int oc = rem - pw*20;
                        C[(size_t)oc*1036800 + (size_t)(gh*16 + ph)*1440 + (gw*16 + pw)]
                            = (e == 0 ? v0 : v1);
                    }
                } else {
                    float2 fv; fv.x = v0; fv.y = v1;
                    *(float2*)&C[(size_t)row*N + c0] = fv;
                }
            }
        }
    }
    if (MODE == 3 || MODE == 4) {
        #pragma unroll
        for (int mt = 0; mt < 2; mt++) {
            #pragma unroll
            for (int h = 0; h < 2; h++) {
                float s = st_s[mt][h], q = st_q[mt][h];
                s += __shfl_xor_sync(0xffffffffu, s, 1);
                q += __shfl_xor_sync(0xffffffffu, q, 1);
                s += __shfl_xor_sync(0xffffffffu, s, 2);
                q += __shfl_xor_sync(0xffffffffu, q, 2);
                const int row = bm + wm*32 + mt*16 + (lane >> 2) + h*8;
                if ((lane & 3) == 0 && row < Mtrue) {
                    atomicAdd(&g_ssum[row], s);
                    atomicAdd(&g_ssq[row],  q);
                }
            }
        }
    }
}

// ---------------- LN2 with fp16-pair output (MLP half); also zeroes LN1 accumulators --------
__global__ void ln_h(const float* __restrict__ in,
                     __half* __restrict__ oh, __half* __restrict__ ol,
                     const float* __restrict__ w, const float* __restrict__ b)
{
    int tok = blockIdx.x;
    int tid = threadIdx.x;
    const float* row = in + (size_t)tok*EE;
    float x0 = row[tid], x1 = row[tid+256], x2 = row[tid+512];
    float s  = x0+x1+x2;
    float sq = x0*x0 + x1*x1 + x2*x2;
    #pragma unroll
    for (int o = 16; o > 0; o >>= 1) {
        s  += __shfl_down_sync(0xffffffffu, s,  o);
        sq += __shfl_down_sync(0xffffffffu, sq, o);
    }
    __shared__ float ss[8], ssq[8];
    int warp = tid >> 5, lane = tid & 31;
    if (lane == 0) { ss[warp] = s; ssq[warp] = sq; }
    __syncthreads();
    if (tid == 0) {
        float ts = 0.f, tq = 0.f;
        #pragma unroll
        for (int i = 0; i < 8; i++) { ts += ss[i]; tq += ssq[i]; }
        float m = ts * (1.0f/768.0f);
        float v = tq * (1.0f/768.0f) - m*m;
        ss[0] = m; ssq[0] = rsqrtf(v + 1e-5f);
        g_ssum[tok] = 0.f;
        g_ssq[tok]  = 0.f;
    }
    __syncthreads();
    float m = ss[0], inv = ssq[0];
    size_t base = (size_t)tok*EE;
    #pragma unroll
    for (int j = 0; j < 3; j++) {
        int o = tid + j*256;
        float y = (j==0?x0:(j==1?x1:x2));
        y = (y - m)*inv*w[o] + b[o];
        __half h, l; hsplit(y, h, l);
        oh[base + o] = h; ol[base + o] = l;
    }
}

// ---------------- DHT stage kernels (LN fused via sums) ----------------
__global__ void k_wfwd(const float* __restrict__ nw, const float* __restrict__ nb) {
    extern __shared__ float sm[];          // 90*128 + 180
    float* stat = sm + 90*128;
    int c0 = blockIdx.x*128, h = blockIdx.y, tid = threadIdx.x;
    if (tid < 90) {
        float mu, ri;
        ln_from_sums(h*90+tid, mu, ri);
        stat[tid]    = mu;
        stat[90+tid] = ri;
    }
    __syncthreads();
    float wv = nw[c0+tid], bv = nb[c0+tid];
    for (int w = 0; w < 90; w++) {
        float av = g_A[(h*90+w)*EE + c0+tid];
        sm[w*128+tid] = (av - stat[w]) * stat[90+w] * wv + bv;
    }
    __syncthreads();
    for (int kw = 0; kw < 23; kw++) {
        float ar = 0.f, ai = 0.f;
        #pragma unroll 6
        for (int w = 0; w < 90; w++) {
            float v = sm[w*128+tid];
            ar += v * g_WC[kw*90+w];
            ai -= v * g_WS[kw*90+w];
        }
        g_Qr[(h*23+kw)*EE + c0+tid] = ar;
        g_Qi[(h*23+kw)*EE + c0+tid] = ai;
    }
}
__global__ void k_hfwd() {
    extern __shared__ float sm[];
    float* sr = sm; float* si = sm + 45*128;
    int c0 = blockIdx.x*128, kw = blockIdx.y, tid = threadIdx.x;
    for (int h = 0; h < 45; h++) {
        sr[h*128+tid] = g_Qr[(h*23+kw)*EE + c0+tid];
        si[h*128+tid] = g_Qi[(h*23+kw)*EE + c0+tid];
    }
    __syncthreads();
    for (int kh = 0; kh < 45; kh++) {
        float qr = 0.f, qi = 0.f;
        #pragma unroll 5
        for (int h = 0; h < 45; h++) {
            float ch = g_HC[kh*45+h], sh = g_HS[kh*45+h];
            float ur = sr[h*128+tid], ui = si[h*128+tid];
            qr += ur*ch + ui*sh;
            qi += ui*ch - ur*sh;
        }
        size_t row = (size_t)(kh*23+kw) * (2*EE);
        __half h2, l2;
        hsplit(qr, h2, l2); g_q2h[row + c0+tid] = h2;      g_q2l[row + c0+tid] = l2;
        hsplit(qi, h2, l2); g_q2h[row + EE + c0+tid] = h2; g_q2l[row + EE + c0+tid] = l2;
    }
}
__global__ void k_hinv2() {
    extern __shared__ float sm[];
    float* tr = sm; float* ti = sm + 45*128;
    int c0 = blockIdx.x*128, wp = blockIdx.y, tid = threadIdx.x;
    for (int hp = 0; hp < 45; hp++) {
        size_t row = (size_t)(hp*23+wp) * (2*EE);
        tr[hp*128+tid] = g_T[row + c0+tid]      + g_T[(size_t)NP*EE + row + c0+tid];
        ti[hp*128+tid] = g_T[row + EE + c0+tid] + g_T[(size_t)NP*EE + row + EE + c0+tid];
    }
    __syncthreads();
    for (int a = 0; a < 45; a++) {
        float zr = 0.f, zi = 0.f;
        #pragma unroll 5
        for (int hp = 0; hp < 45; hp++) {
            float ch = g_HC[a*45+hp], sh = g_HS[a*45+hp];
            float xr = tr[hp*128+tid], xi = ti[hp*128+tid];
            zr += xr*ch + xi*sh;
            zi += xi*ch - xr*sh;
        }
        g_Zr[(a*23+wp)*EE + c0+tid] = zr;
        g_Zi[(a*23+wp)*EE + c0+tid] = zi;
    }
}
// inverse W-stage: A += y + LN1(A) (normalization recomputed from sums)
__global__ void k_winv2(const float* __restrict__ nw, const float* __restrict__ nb) {
    extern __shared__ float sm[];
    float* zr = sm; float* zi = sm + 23*128;
    int c0 = blockIdx.x*128, a = blockIdx.y, tid = threadIdx.x;
    for (int wp = 0; wp < 23; wp++) {
        zr[wp*128+tid] = g_Zr[(a*23+wp)*EE + c0+tid];
        zi[wp*128+tid] = g_Zi[(a*23+wp)*EE + c0+tid];
    }
    __syncthreads();
    float wv = nw[c0+tid], bv = nb[c0+tid];
    for (int b = 0; b < 90; b++) {
        float y = 0.f;
        #pragma unroll
        for (int wp = 0; wp < 23; wp++) {
            y += zr[wp*128+tid]*g_WCm[b*90+wp] + zi[wp*128+tid]*g_WCp[b*90+wp];
        }
        int tok = a*90 + b;
        size_t idx = (size_t)tok*EE + c0+tid;
        float mu, ri;
        ln_from_sums(tok, mu, ri);
        float av = g_A[idx];
        float tv = (av - mu) * ri * wv + bv;
        g_A[idx] = av + y + tv;
    }
}

// ---------------- misc elementwise ----------------
__global__ void im2col_kernel(const float* __restrict__ x) {
    int idx = blockIdx.x*256 + threadIdx.x;
    if (idx >= NP*PKK) return;
    int p = idx / PKK, k = idx % PKK;
    int c = k >> 8, r = k & 255;
    int ph = r >> 4, pw = r & 15;
    int gh = p / 90, gw = p % 90;
    float v = x[(size_t)c*1036800 + (size_t)(gh*16+ph)*1440 + (gw*16+pw)];
    __half h, l; hsplit(v, h, l);
    size_t o = (size_t)p*PKK + k;
    g_pxh[o] = h; g_pxl[o] = l;
}

// ---------------- block-weight prep, ALL layers hoisted ----------------
__global__ void prep_pm_all(const float* __restrict__ w1, const float* __restrict__ w2) {
    int idx = blockIdx.x*256 + threadIdx.x;
    if (idx >= 12*BLK) return;
    int l = idx / BLK, i = idx % BLK;
    const float* w1l = w1 + (size_t)l*2*BLK;
    const float* w2l = w2 + (size_t)l*2*BLK;
    g_W1p[idx] = 0.5f*(w1l[i] + w1l[BLK+i]);
    g_W1m[idx] = 0.5f*(w1l[i] - w1l[BLK+i]);
    g_W2p[idx] = 0.5f*(w2l[i] + w2l[BLK+i]);
    g_W2m[idx] = 0.5f*(w2l[i] - w2l[BLK+i]);
}
__global__ void prep_ab_all() {
    int idx = blockIdx.x*128 + threadIdx.x;
    if (idx >= 12*BLK) return;
    int l = idx / BLK, rr = idx % BLK;
    int o = rr % 96;
    int i = (rr / 96) % 96;
    int b = rr / 9216;
    const float* P = g_W2p + (size_t)l*BLK + b*9216;
    const float* M = g_W2m + (size_t)l*BLK + b*9216;
    float aa = g_W2p[idx];
    float bb = g_W2m[idx] + g_W2p[idx];
    #pragma unroll 8
    for (int j = 0; j < 96; j++) {
        aa += P[i*96+j] * M[j*96+o];
        bb += M[i*96+j] * M[j*96+o];
    }
    g_W2a[idx] = aa;
    g_W2b[idx] = bb;
}
__global__ void prep_bs_all(const float* __restrict__ b2) {
    int idx = blockIdx.x*128 + threadIdx.x;
    if (idx >= 12*NBB*BSS) return;
    int l = idx / (NBB*BSS), rr = idx % (NBB*BSS);
    int o = rr % 96, b = rr / 96;
    const float* b2l = b2 + (size_t)l*2*NBB*BSS;
    float v = b2l[rr] + b2l[NBB*BSS + rr];
    const float* M = g_W2m + (size_t)l*BLK;
    #pragma unroll 8
    for (int j = 0; j < 96; j++) v += b2l[b*96+j] * M[(b*96+j)*96+o];
    g_bs[idx] = v;
}

// ---------------- fused block mixing (LN-gather + mix1 + mix2 + soft-thresh + split) ----------------
#define MROWS 45
#define MIXSM ((9216*2 + MROWS*96*2)*4)
__global__ void k_mixf(const float* __restrict__ b1l,
                       const float* __restrict__ nw, const float* __restrict__ nb,
                       int loff, int lbs) {
    extern __shared__ float sm[];
    float* sW1 = sm;
    float* sW2 = sm + 9216;
    float* sX  = sm + 18432;
    float* sY  = sX + MROWS*96;
    int b = blockIdx.x, tile = blockIdx.y;
    int t = threadIdx.x;
    int o = t % 96, rg = t / 96;
    for (int i = t; i < 9216; i += 288) {
        sW1[i] = g_W1p[loff + b*9216+i];
        sW2[i] = g_W1m[loff + b*9216+i];
    }
    int p0 = tile * MROWS;
    float nwv = nw[b*96+o], nbv = nb[b*96+o];
    for (int pp = rg; pp < MROWS; pp += 3) {
        int p = p0 + pp;
        int h = p / 23, w = p % 23;
        int shh = (45 - h) % 45;
        int sww = (90 - w) % 90;
        int tok = shh*90 + sww;
        float mu, ri;
        ln_from_sums(tok, mu, ri);
        float av = g_A[(size_t)tok*EE + b*96 + o];
        sX[pp*96+o] = g_a[(size_t)p*EE + b*96 + o] + g_a[(size_t)NFREQ*EE + (size_t)p*EE + b*96 + o];
        sY[pp*96+o] = (av - mu) * ri * nwv + nbv;
    }
    __syncthreads();
    float bk = b1l[b*96+o], bn = b1l[NBB*BSS + b*96+o];
    float ok_[15], on_[15];
    {
        int c = 0;
        for (int pp = rg; pp < MROWS; pp += 3, c++) {
            float ak = bk, an = bn;
            #pragma unroll 8
            for (int i = 0; i < 96; i++) {
                float xv = sX[pp*96+i], yv = sY[pp*96+i];
                float wp = sW1[i*96+o], wm = sW2[i*96+o];
                ak += xv*wp + yv*wm;
                an += yv*wp + xv*wm;
            }
            ok_[c] = fmaxf(ak, 0.f);
            on_[c] = fmaxf(an, 0.f);
        }
    }
    __syncthreads();
    {
        int c = 0;
        for (int pp = rg; pp < MROWS; pp += 3, c++) {
            sX[pp*96+o] = ok_[c];
            sY[pp*96+o] = on_[c];
        }
    }
    for (int i = t; i < 9216; i += 288) {
        sW1[i] = g_W2a[loff + b*9216+i];
        sW2[i] = g_W2b[loff + b*9216+i];
    }
    __syncthreads();
    float bsv = g_bs[lbs + b*96+o];
    for (int pp = rg; pp < MROWS; pp += 3) {
        float acc = bsv;
        #pragma unroll 8
        for (int i = 0; i < 96; i++) {
            acc += sX[pp*96+i]*sW1[i*96+o] + sY[pp*96+i]*sW2[i*96+o];
        }
        float aab = fabsf(acc) - 0.01f;
        float v = (aab > 0.f) ? copysignf(aab, acc) : 0.f;
        __half h, l; hsplit(v, h, l);
        size_t idx = (size_t)(p0+pp)*EE + b*96 + o;
        g_sh[idx] = h; g_sl[idx] = l;
    }
}

// ---------------- host orchestration ----------------
extern "C" void kernel_launch(void* const* d_in, const int* in_sizes, int n_in,
                              void* d_out, int out_size)
{
    const float* x        = (const float*)d_in[0];
    const float* patch_w  = (const float*)d_in[1];
    const float* patch_b  = (const float*)d_in[2];
    const float* pos      = (const float*)d_in[3];
    const float* norm1_w  = (const float*)d_in[4];
    const float* norm1_b  = (const float*)d_in[5];
    const float* w1       = (const float*)d_in[6];
    const float* b1       = (const float*)d_in[7];
    const float* w2       = (const float*)d_in[8];
    const float* b2       = (const float*)d_in[9];
    const float* norm2_w  = (const float*)d_in[10];
    const float* norm2_b  = (const float*)d_in[11];
    const float* fc1_w    = (const float*)d_in[12];
    const float* fc1_b    = (const float*)d_in[13];
    const float* fc2_w    = (const float*)d_in[14];
    const float* fc2_b    = (const float*)d_in[15];
    const float* head_w   = (const float*)d_in[16];
    float* out = (float*)d_out;

    float *pA,*pTT,*pa;
    cudaGetSymbolAddress((void**)&pA,  g_A);
    cudaGetSymbolAddress((void**)&pTT, g_T);
    cudaGetSymbolAddress((void**)&pa,  g_a);

    __half *pxh,*pxl,*th,*tl,*hbh,*hbl,*ah2,*al2,*q2h,*q2l,*sh,*sl;
    __half *pw,*fB,*iB,*f1,*f2,*hw;
    cudaGetSymbolAddress((void**)&pxh, g_pxh);  cudaGetSymbolAddress((void**)&pxl, g_pxl);
    cudaGetSymbolAddress((void**)&th,  g_th);   cudaGetSymbolAddress((void**)&tl,  g_tl);
    cudaGetSymbolAddress((void**)&hbh, g_hbh);  cudaGetSymbolAddress((void**)&hbl, g_hbl);
    cudaGetSymbolAddress((void**)&ah2, g_Ah2);  cudaGetSymbolAddress((void**)&al2, g_Al2);
    cudaGetSymbolAddress((void**)&q2h, g_q2h);  cudaGetSymbolAddress((void**)&q2l, g_q2l);
    cudaGetSymbolAddress((void**)&sh,  g_sh);   cudaGetSymbolAddress((void**)&sl,  g_sl);
    cudaGetSymbolAddress((void**)&pw,  g_pw);
    cudaGetSymbolAddress((void**)&fB,  g_fB);
    cudaGetSymbolAddress((void**)&iB,  g_iB);
    cudaGetSymbolAddress((void**)&f1,  g_f1);
    cudaGetSymbolAddress((void**)&f2,  g_f2);
    cudaGetSymbolAddress((void**)&hw,  g_hw);

    cudaFuncSetAttribute(k_wfwd,  cudaFuncAttributeMaxDynamicSharedMemorySize, 90*128*4 + 180*4);
    cudaFuncSetAttribute(k_hfwd,  cudaFuncAttributeMaxDynamicSharedMemorySize, 2*45*128*4);
    cudaFuncSetAttribute(k_hinv2, cudaFuncAttributeMaxDynamicSharedMemorySize, 2*45*128*4);
    cudaFuncSetAttribute(k_winv2, cudaFuncAttributeMaxDynamicSharedMemorySize, 2*23*128*4);
    cudaFuncSetAttribute(k_mixf,  cudaFuncAttributeMaxDynamicSharedMemorySize, MIXSM);
    const int SMB64  = 2*(2*A_TB + 64*SMSTR*2);    // 51200
    const int SMB128 = 2*(2*A_TB + 128*SMSTR*2);   // 61440
    cudaFuncSetAttribute((const void*)hgemm<0,64>,  cudaFuncAttributeMaxDynamicSharedMemorySize, SMB64);
    cudaFuncSetAttribute((const void*)hgemm<3,64>,  cudaFuncAttributeMaxDynamicSharedMemorySize, SMB64);
    cudaFuncSetAttribute((const void*)hgemm<4,64>,  cudaFuncAttributeMaxDynamicSharedMemorySize, SMB64);
    cudaFuncSetAttribute((const void*)hgemm<5,64>,  cudaFuncAttributeMaxDynamicSharedMemorySize, SMB64);
    cudaFuncSetAttribute((const void*)hgemm<2,128>, cudaFuncAttributeMaxDynamicSharedMemorySize, SMB128);
    cudaFuncSetAttribute((const void*)hgemm<6,128>, cudaFuncAttributeMaxDynamicSharedMemorySize, SMB128);

    // tables + weight converts + ALL-layer block-weight prep (once)
    tabC <<<(EE*EE + 255)/256, 256>>>();
    tab90<<<(GWw*GWw + 255)/256, 256>>>();
    tab45<<<(GHh*GHh + 255)/256, 256>>>();
    conv_kernel<<<(EE*PKK + 255)/256, 256>>>(patch_w, pw, EE*PKK);
    conv_kernel<<<(HDD*EE + 255)/256, 256>>>(head_w, hw, HDD*EE);
    conv_kernel<<<(12*HID*EE + 255)/256, 256>>>(fc1_w, f1, 12*HID*EE);
    conv_kernel<<<(12*EE*HID + 255)/256, 256>>>(fc2_w, f2, 12*EE*HID);
    prep_pm_all<<<(12*BLK + 255)/256, 256>>>(w1, w2);
    prep_ab_all<<<(12*BLK + 127)/128, 128>>>();
    prep_bs_all<<<(12*NBB*BSS + 127)/128, 128>>>(b2);

    const dim3 GB(256);

    // patch embed (bias + pos fused; emits LN1 stats for layer 0)
    im2col_kernel<<<(NP*PKK + 255)/256, 256>>>(x);
    hgemm<4,64><<<dim3(EE/64, MPAD/128), GB, SMB64>>>(pxh, pxl, pw, pA, nullptr, nullptr,
                                                      NP, EE, PKK, patch_b, pos, PKK, 0);

    for (int l = 0; l < 12; l++) {
        // ---- AFNO half ----
        k_wfwd<<<dim3(6, 45), 128, 90*128*4 + 180*4>>>(norm1_w + l*EE, norm1_b + l*EE);
        k_hfwd<<<dim3(6, 23), 128, 2*45*128*4>>>();
        // fwd C-stage GEMM: split-K2 (z=0: Q2r x (cos-sin); z=1: Q2i x (cos+sin))
        hgemm<0,64><<<dim3(EE/64, FPAD/128, 2), GB, SMB64>>>(q2h, q2l, fB, pa, nullptr, nullptr,
                                                             NFREQ, EE, EE, nullptr, nullptr,
                                                             2*EE, (long)NFREQ*EE);
        k_mixf<<<dim3(8, 23), 288, MIXSM>>>(b1 + (size_t)l*2*NBB*BSS,
                                            norm1_w + l*EE, norm1_b + l*EE, l*BLK, l*NBB*BSS);
        // inv C-stage GEMM: split-K2 over the 768 c-dimension
        hgemm<0,64><<<dim3((2*EE)/64, FPAD/128, 2), GB, SMB64>>>(sh, sl, iB, pTT, nullptr, nullptr,
                                                                 NFREQ, 2*EE, EE/2, nullptr, nullptr,
                                                                 EE, (long)NP*EE);
        k_hinv2<<<dim3(6, 23), 128, 2*45*128*4>>>();
        k_winv2<<<dim3(6, 45), 128, 2*23*128*4>>>(norm1_w + l*EE, norm1_b + l*EE);

        // ---- MLP half ----
        ln_h<<<NP, 256>>>(pA, th, tl, norm2_w + l*EE, norm2_b + l*EE);
        hgemm<2,128><<<dim3(HID/128, MPAD/128), GB, SMB128>>>(th, tl, f1 + (size_t)l*HID*EE,
                                                              nullptr, hbh, hbl, NP, HID, EE, fc1_b + l*HID, nullptr,
                                                              EE, 0);
        if (l < 11) {
            hgemm<3,64><<<dim3(EE/64, MPAD/128), GB, SMB64>>>(hbh, hbl, f2 + (size_t)l*EE*HID,
                                                              pA, nullptr, nullptr, NP, EE, HID, fc2_b + l*EE, nullptr,
                                                              HID, 0);
        } else {
            hgemm<5,64><<<dim3(EE/64, MPAD/128), GB, SMB64>>>(hbh, hbl, f2 + (size_t)l*EE*HID,
                                                              pA, ah2, al2, NP, EE, HID, fc2_b + l*EE, nullptr,
                                                              HID, 0);
        }
    }

    // head: GEMM scatters directly into the output image
    hgemm<6,128><<<dim3(HDD/128, MPAD/128), GB, SMB128>>>(ah2, al2, hw, out, nullptr, nullptr,
                                                          NP, HDD, EE, nullptr, nullptr, EE, 0);
}

// round 17
// speedup vs baseline: 1.1773x; 1.0022x over previous
#include <cuda_runtime.h>
#include <cuda_fp16.h>
#include <math.h>
#include <stdint.h>

// ---------------- constants ----------------
#define GHh 45
#define GWw 90
#define NP 4050          // tokens
#define MPAD 4096        // padded token rows
#define EE 768
#define KM 23
#define NFREQ (GHh*KM)   // 1035
#define FPAD 1152        // padded freq rows (9*128)
#define HID 3072
#define PKK 5120
#define HDD 5120
#define NBB 8
#define BSS 96
#define BLK (NBB*BSS*BSS)   // 73728 per layer
#define DHT_SIZE 3110400.0

// ---------------- fp32 scratch ----------------
__device__ __align__(128) float g_A [NP*EE];
__device__ __align__(128) float g_T [2*(size_t)NP*EE];
__device__ __align__(128) float g_Qr[NFREQ*EE];
__device__ __align__(128) float g_Qi[NFREQ*EE];
__device__ __align__(128) float g_Zr[NFREQ*EE];
__device__ __align__(128) float g_Zi[NFREQ*EE];
__device__ __align__(128) float g_a [2*(size_t)NFREQ*EE];
__device__ __align__(128) float g_ssum[NP];
__device__ __align__(128) float g_ssq [NP];
// small DFT tables
__device__ __align__(128) float g_WC[GWw*GWw];
__device__ __align__(128) float g_WS[GWw*GWw];
__device__ __align__(128) float g_WCm[GWw*GWw];
__device__ __align__(128) float g_WCp[GWw*GWw];
__device__ __align__(128) float g_HC[GHh*GHh];
__device__ __align__(128) float g_HS[GHh*GHh];
// per-layer prepped block weights (ALL 12 layers, hoisted)
__device__ __align__(128) float g_W1p[12*BLK], g_W1m[12*BLK];
__device__ __align__(128) float g_W2p[12*BLK], g_W2m[12*BLK];
__device__ __align__(128) float g_W2a[12*BLK], g_W2b[12*BLK];
__device__ __align__(128) float g_bs [12*NBB*BSS];

// ---------------- fp16 buffers: activations as hi/lo pairs, weights single ----------------
__device__ __align__(128) __half g_pxh[(size_t)MPAD*PKK], g_pxl[(size_t)MPAD*PKK];
__device__ __align__(128) __half g_th [(size_t)MPAD*EE],  g_tl [(size_t)MPAD*EE];
__device__ __align__(128) __half g_hbh[(size_t)MPAD*HID], g_hbl[(size_t)MPAD*HID];
__device__ __align__(128) __half g_Ah2[(size_t)MPAD*EE],  g_Al2[(size_t)MPAD*EE];
__device__ __align__(128) __half g_q2h[(size_t)FPAD*2*EE], g_q2l[(size_t)FPAD*2*EE];
__device__ __align__(128) __half g_sh [(size_t)FPAD*EE],  g_sl [(size_t)FPAD*EE];
// weights / tables (single fp16)
__device__ __align__(128) __half g_pw [EE*PKK];
__device__ __align__(128) __half g_fB [EE*2*EE];
__device__ __align__(128) __half g_iB [2*EE*EE];
__device__ __align__(128) __half g_f1 [(size_t)12*HID*EE];
__device__ __align__(128) __half g_f2 [(size_t)12*EE*HID];
__device__ __align__(128) __half g_hw [HDD*EE];

// ---------------- helpers ----------------
__device__ __forceinline__ void hsplit(float x, __half& h, __half& l) {
    h = __float2half(x);
    l = __float2half(x - __half2float(h));
}
__device__ __forceinline__ uint32_t s2u32(const void* p) {
    uint32_t a;
    asm("{ .reg .u64 t; cvta.to.shared.u64 t, %1; cvt.u32.u64 %0, t; }" : "=r"(a) : "l"(p));
    return a;
}
__device__ __forceinline__ void mma_f16(float* c, const uint32_t* a, const uint32_t* b) {
    asm volatile("mma.sync.aligned.m16n8k16.row.col.f32.f16.f16.f32 "
        "{%0,%1,%2,%3}, {%4,%5,%6,%7}, {%8,%9}, {%0,%1,%2,%3};"
        : "+f"(c[0]), "+f"(c[1]), "+f"(c[2]), "+f"(c[3])
        : "r"(a[0]), "r"(a[1]), "r"(a[2]), "r"(a[3]), "r"(b[0]), "r"(b[1]));
}
__device__ __forceinline__ void cpa16(uint32_t dst, const void* src) {
    asm volatile("cp.async.cg.shared.global [%0], [%1], 16;" :: "r"(dst), "l"(src));
}
__device__ __forceinline__ void ldsm4(uint32_t* r, uint32_t addr) {
    asm volatile("ldmatrix.sync.aligned.m8n8.x4.shared.b16 {%0,%1,%2,%3}, [%4];"
        : "=r"(r[0]), "=r"(r[1]), "=r"(r[2]), "=r"(r[3]) : "r"(addr));
}
__device__ __forceinline__ void ln_from_sums(int tok, float& mu, float& ri) {
    float s = g_ssum[tok], q = g_ssq[tok];
    mu = s * (1.0f/768.0f);
    float v = q * (1.0f/768.0f) - mu*mu;
    ri = rsqrtf(v + 1e-5f);
}

// ---------------- table init ----------------
__global__ void tabC() {
    int idx = blockIdx.x*256 + threadIdx.x;
    if (idx >= EE*EE) return;
    int kc = idx / EE, c = idx % EE;
    long long m = ((long long)kc * c) % EE;
    double a = 2.0 * (double)m / (double)EE;
    double cs = cospi(a), sn = sinpi(a);
    g_fB[kc*2*EE + c]      = __float2half((float)(cs - sn));
    g_fB[kc*2*EE + EE + c] = __float2half((float)(cs + sn));
    g_iB[kc*EE + c]        = __float2half((float)cs);
    g_iB[(EE+kc)*EE + c]   = __float2half((float)(-sn));
}
__global__ void tab90() {
    int idx = blockIdx.x*256 + threadIdx.x;
    if (idx >= GWw*GWw) return;
    int a = idx / GWw, b = idx % GWw;
    long long m = ((long long)a * b) % GWw;
    double ang = 2.0 * (double)m / (double)GWw;
    double cs = cospi(ang), sn = sinpi(ang);
    g_WC[idx]  = (float)cs;
    g_WS[idx]  = (float)sn;
    g_WCm[idx] = (float)((cs - sn) / DHT_SIZE);
    g_WCp[idx] = (float)((cs + sn) / DHT_SIZE);
}
__global__ void tab45() {
    int idx = blockIdx.x*256 + threadIdx.x;
    if (idx >= GHh*GHh) return;
    int a = idx / GHh, b = idx % GHh;
    long long m = ((long long)a * b) % GHh;
    double ang = 2.0 * (double)m / (double)GHh;
    g_HC[idx] = (float)cospi(ang);
    g_HS[idx] = (float)sinpi(ang);
}

__global__ void conv_kernel(const float* __restrict__ in, __half* __restrict__ o, int n) {
    int i = blockIdx.x*256 + threadIdx.x;
    if (i >= n) return;
    o[i] = __float2half(in[i]);
}

// ---------------- fp16x2 mma.sync GEMM, tile 128M x NT(64|128), k-chunk 32, split-K ----
// A = (Ah + Al) fp16 pair, B single fp16. D = Ah*B + Al*B.
// NT=64: double-buffer, 2 syncs/chunk, 3 CTAs/SM.
// NT=128: 3-stage cp.async ring, 1 sync/chunk, 2 CTAs/SM.
// MODE: 0=store fp32 (+split-K via blockIdx.z), 2=bias+GELU->fp16 pair,
//       3=accumulate(+bias) fp32 + LN stats, 4=store+bias+addmat + LN stats,
//       5=accumulate(+bias) fp32 AND emit fp16 pair, 6=head scatter to output image
#define SMSTR 40
#define A_TB (128*SMSTR*2)

template<int MODE, int NT = 64>
__global__ void __launch_bounds__(256, (NT == 64) ? 3 : 2)
hgemm(const __half* __restrict__ Ah, const __half* __restrict__ Al,
      const __half* __restrict__ B,
      float* __restrict__ C,
      __half* __restrict__ Csh, __half* __restrict__ Csl,
      int Mtrue, int N, int K, const float* __restrict__ bias,
      const float* __restrict__ addm, int ld, long zoff)
{
    constexpr int B_TBX = NT*SMSTR*2;
    constexpr int BUFB  = 2*A_TB + B_TBX;
    constexpr int NBUF  = (NT == 64) ? 2 : 3;
    constexpr int WNT   = NT/16;
    constexpr int NJ    = WNT/2;

    extern __shared__ __align__(128) char smem[];
    const int t = threadIdx.x, warp = t >> 5, lane = t & 31;
    const int wm = warp >> 1, wn = warp & 1;
    const int bm = blockIdx.y * 128, bn = blockIdx.x * NT;
    const int kz = blockIdx.z;
    const size_t kbase = (size_t)kz * K;
    if (MODE == 0) C += (size_t)kz * zoff;
    const uint32_t sb = s2u32(smem);

    float acc[2][WNT][4];
    #pragma unroll
    for (int i = 0; i < 2; i++)
        #pragma unroll
        for (int j = 0; j < WNT; j++)
            #pragma unroll
            for (int q = 0; q < 4; q++) acc[i][j][q] = 0.f;

    const int arow = t & 127, ahalf = t >> 7;
    const __half* pAh = Ah + (size_t)(bm + arow) * ld + kbase + ahalf * 16;
    const __half* pAl = Al + (size_t)(bm + arow) * ld + kbase + ahalf * 16;
    const uint32_t aoff = (uint32_t)(arow * SMSTR + ahalf * 16) * 2;
    const __half* pB;
    uint32_t boff;
    if (NT == 64) {
        const int brow = t >> 2, bseg = t & 3;
        pB = B + (size_t)(bn + brow) * ld + kbase + bseg * 8;
        boff = (uint32_t)(brow * SMSTR + bseg * 8) * 2;
    } else {
        const int brow = t & 127, bhalf = t >> 7;
        pB = B + (size_t)(bn + brow) * ld + kbase + bhalf * 16;
        boff = (uint32_t)(brow * SMSTR + bhalf * 16) * 2;
    }

    // precomputed LDSM base addresses (buffer 0); in-loop: + buffer offset
    uint32_t adA[2][2], adB[2][NJ];
    {
        const int g = lane >> 3, r = lane & 7;
        #pragma unroll
        for (int step = 0; step < 2; step++) {
            const int ks = step * 16;
            const uint32_t a_off = (uint32_t)(((g & 1) * 8 + r) * SMSTR + ks + (g >> 1) * 8) * 2;
            const uint32_t b_off = (uint32_t)(((g >> 1) * 8 + r) * SMSTR + ks + (g & 1) * 8) * 2;
            #pragma unroll
            for (int mt = 0; mt < 2; mt++)
                adA[step][mt] = sb + (uint32_t)((wm*32 + mt*16) * SMSTR) * 2 + a_off;
            #pragma unroll
            for (int j2 = 0; j2 < NJ; j2++)
                adB[step][j2] = sb + 2*A_TB + (uint32_t)((wn*(NT/2) + j2*16) * SMSTR) * 2 + b_off;
        }
    }

    const int nch = K >> 5;
    auto issue = [&](int ch, uint32_t bufo) {
        const int k0 = ch << 5;
        const uint32_t dst = sb + bufo;
        cpa16(dst + aoff,        pAh + k0); cpa16(dst + aoff + 16,        pAh + k0 + 8);
        cpa16(dst + A_TB + aoff, pAl + k0); cpa16(dst + A_TB + aoff + 16, pAl + k0 + 8);
        if (NT == 64) {
            cpa16(dst + 2*A_TB + boff, pB + k0);
        } else {
            cpa16(dst + 2*A_TB + boff,      pB + k0);
            cpa16(dst + 2*A_TB + boff + 16, pB + k0 + 8);
        }
        asm volatile("cp.async.commit_group;" ::: "memory");
    };
    auto compute = [&](uint32_t bsel) {
        #pragma unroll
        for (int step = 0; step < 2; step++) {
            uint32_t b_[WNT][2];
            #pragma unroll
            for (int j2 = 0; j2 < NJ; j2++) {
                uint32_t tmp[4];
                ldsm4(tmp, adB[step][j2] + bsel);
                b_[j2*2][0]=tmp[0]; b_[j2*2][1]=tmp[1]; b_[j2*2+1][0]=tmp[2]; b_[j2*2+1][1]=tmp[3];
            }
            #pragma unroll
            for (int mt = 0; mt < 2; mt++) {
                const uint32_t ad = adA[step][mt] + bsel;
                uint32_t ah_[4], al_[4];
                ldsm4(ah_, ad);
                ldsm4(al_, ad + A_TB);
                #pragma unroll
                for (int nt = 0; nt < WNT; nt++) mma_f16(acc[mt][nt], ah_, b_[nt]);
                #pragma unroll
                for (int nt = 0; nt < WNT; nt++) mma_f16(acc[mt][nt], al_, b_[nt]);
            }
        }
    };

    if (NBUF == 2) {
        issue(0, 0);
        for (int ch = 0; ch < nch; ch++) {
            const bool more = (ch + 1) < nch;
            if (more) { issue(ch + 1, (uint32_t)((ch+1) & 1) * BUFB);
                        asm volatile("cp.async.wait_group 1;" ::: "memory"); }
            else      { asm volatile("cp.async.wait_group 0;" ::: "memory"); }
            __syncthreads();
            compute((uint32_t)(ch & 1) * BUFB);
            __syncthreads();
        }
    } else {
        issue(0, 0);
        if (nch > 1) issue(1, BUFB);
        uint32_t rbo = 0, wbo = 2*BUFB;
        for (int ch = 0; ch < nch; ch++) {
            if (ch + 1 < nch) asm volatile("cp.async.wait_group 1;" ::: "memory");
            else              asm volatile("cp.async.wait_group 0;" ::: "memory");
            __syncthreads();
            if (ch + 2 < nch) {
                issue(ch + 2, wbo);
                wbo += BUFB; if (wbo == 3u*BUFB) wbo = 0;
            }
            compute(rbo);
            rbo += BUFB; if (rbo == 3u*BUFB) rbo = 0;
        }
    }

    // epilogue
    float st_s[2][2], st_q[2][2];
    if (MODE == 3 || MODE == 4) {
        #pragma unroll
        for (int i = 0; i < 2; i++)
            #pragma unroll
            for (int j = 0; j < 2; j++) { st_s[i][j] = 0.f; st_q[i][j] = 0.f; }
    }
    #pragma unroll
    for (int mt = 0; mt < 2; mt++) {
        const int r0 = bm + wm*32 + mt*16 + (lane >> 2);
        #pragma unroll
        for (int nt = 0; nt < WNT; nt++) {
            const int c0 = bn + wn*(NT/2) + nt*8 + (lane & 3)*2;
            float b0 = 0.f, b1 = 0.f;
            if (MODE == 2 || MODE == 3 || MODE == 4 || MODE == 5) { b0 = bias[c0]; b1 = bias[c0+1]; }
            #pragma unroll
            for (int h = 0; h < 2; h++) {
                const int row = r0 + h*8;
                if (row >= Mtrue) continue;
                float v0 = acc[mt][nt][h*2+0] + b0;
                float v1 = acc[mt][nt][h*2+1] + b1;
                if (MODE == 2) {
                    v0 = 0.5f*v0*(1.0f + erff(v0*0.7071067811865475f));
                    v1 = 0.5f*v1*(1.0f + erff(v1*0.7071067811865475f));
                    __half h0, l0, h1, l1;
                    hsplit(v0, h0, l0); hsplit(v1, h1, l1);
                    __half2 hv; hv.x = h0; hv.y = h1;
                    __half2 lv; lv.x = l0; lv.y = l1;
                    *(__half2*)&Csh[(size_t)row*N + c0] = hv;
                    *(__half2*)&Csl[(size_t)row*N + c0] = lv;
                } else if (MODE == 3) {
                    float2* cp = (float2*)&C[(size_t)row*N + c0];
                    float2 old = *cp;
                    old.x += v0; old.y += v1;
                    *cp = old;
                    st_s[mt][h] += old.x + old.y;
                    st_q[mt][h] += old.x*old.x + old.y*old.y;
                } else if (MODE == 5) {
                    float2* cp = (float2*)&C[(size_t)row*N + c0];
                    float2 old = *cp;
                    old.x += v0; old.y += v1;
                    *cp = old;
                    __half h0, l0, h1, l1;
                    hsplit(old.x, h0, l0); hsplit(old.y, h1, l1);
                    __half2 hv; hv.x = h0; hv.y = h1;
                    __half2 lv; lv.x = l0; lv.y = l1;
                    *(__half2*)&Csh[(size_t)row*N + c0] = hv;
                    *(__half2*)&Csl[(size_t)row*N + c0] = lv;
                } else if (MODE == 4) {
                    const float2 am = *(const float2*)&addm[(size_t)row*N + c0];
                    float2 fv; fv.x = v0 + am.x; fv.y = v1 + am.y;
                    *(float2*)&C[(size_t)row*N + c0] = fv;
                    st_s[mt][h] += fv.x + fv.y;
                    st_q[mt][h] += fv.x*fv.x + fv.y*fv.y;
                } else if (MODE == 6) {
                    const int gh = row / 90, gw = row % 90;
                    #pragma unroll
                    for (int e = 0; e < 2; e++) {
                        const int n = c0 + e;
                        const int ph = n / 320;
                        const int rem = n - ph*320;
                        const int pw = rem / 20;
                        const int oc = rem - pw*20;
                        C[(size_t)oc*1036800 + (size_t)(gh*16 + ph)*1440 + (gw*16 + pw)]
                            = (e == 0 ? v0 : v1);
                    }
                } else {
                    float2 fv; fv.x = v0; fv.y = v1;
                    *(float2*)&C[(size_t)row*N + c0] = fv;
                }
            }
        }
    }
    if (MODE == 3 || MODE == 4) {
        #pragma unroll
        for (int mt = 0; mt < 2; mt++) {
            #pragma unroll
            for (int h = 0; h < 2; h++) {
                float s = st_s[mt][h], q = st_q[mt][h];
                s += __shfl_xor_sync(0xffffffffu, s, 1);
                q += __shfl_xor_sync(0xffffffffu, q, 1);
                s += __shfl_xor_sync(0xffffffffu, s, 2);
                q += __shfl_xor_sync(0xffffffffu, q, 2);
                const int row = bm + wm*32 + mt*16 + (lane >> 2) + h*8;
                if ((lane & 3) == 0 && row < Mtrue) {
                    atomicAdd(&g_ssum[row], s);
                    atomicAdd(&g_ssq[row],  q);
                }
            }
        }
    }
}

// ---------------- LN2 with fp16-pair output (MLP half); also zeroes LN1 accumulators --------
__global__ void ln_h(const float* __restrict__ in,
                     __half* __restrict__ oh, __half* __restrict__ ol,
                     const float* __restrict__ w, const float* __restrict__ b)
{
    int tok = blockIdx.x;
    int tid = threadIdx.x;
    const float* row = in + (size_t)tok*EE;
    float x0 = row[tid], x1 = row[tid+256], x2 = row[tid+512];
    float s  = x0+x1+x2;
    float sq = x0*x0 + x1*x1 + x2*x2;
    #pragma unroll
    for (int o = 16; o > 0; o >>= 1) {
        s  += __shfl_down_sync(0xffffffffu, s,  o);
        sq += __shfl_down_sync(0xffffffffu, sq, o);
    }
    __shared__ float ss[8], ssq[8];
    int warp = tid >> 5, lane = tid & 31;
    if (lane == 0) { ss[warp] = s; ssq[warp] = sq; }
    __syncthreads();
    if (tid == 0) {
        float ts = 0.f, tq = 0.f;
        #pragma unroll
        for (int i = 0; i < 8; i++) { ts += ss[i]; tq += ssq[i]; }
        float m = ts * (1.0f/768.0f);
        float v = tq * (1.0f/768.0f) - m*m;
        ss[0] = m; ssq[0] = rsqrtf(v + 1e-5f);
        g_ssum[tok] = 0.f;
        g_ssq[tok]  = 0.f;
    }
    __syncthreads();
    float m = ss[0], inv = ssq[0];
    size_t base = (size_t)tok*EE;
    #pragma unroll
    for (int j = 0; j < 3; j++) {
        int o = tid + j*256;
        float y = (j==0?x0:(j==1?x1:x2));
        y = (y - m)*inv*w[o] + b[o];
        __half h, l; hsplit(y, h, l);
        oh[base + o] = h; ol[base + o] = l;
    }
}

// ---------------- DHT stage kernels (LN fused via sums) ----------------
__global__ void k_wfwd(const float* __restrict__ nw, const float* __restrict__ nb) {
    extern __shared__ float sm[];
    float* stat = sm + 90*128;
    int c0 = blockIdx.x*128, h = blockIdx.y, tid = threadIdx.x;
    if (tid < 90) {
        float mu, ri;
        ln_from_sums(h*90+tid, mu, ri);
        stat[tid]    = mu;
        stat[90+tid] = ri;
    }
    __syncthreads();
    float wv = nw[c0+tid], bv = nb[c0+tid];
    for (int w = 0; w < 90; w++) {
        float av = g_A[(h*90+w)*EE + c0+tid];
        sm[w*128+tid] = (av - stat[w]) * stat[90+w] * wv + bv;
    }
    __syncthreads();
    for (int kw = 0; kw < 23; kw++) {
        float ar = 0.f, ai = 0.f;
        #pragma unroll 6
        for (int w = 0; w < 90; w++) {
            float v = sm[w*128+tid];
            ar += v * g_WC[kw*90+w];
            ai -= v * g_WS[kw*90+w];
        }
        g_Qr[(h*23+kw)*EE + c0+tid] = ar;
        g_Qi[(h*23+kw)*EE + c0+tid] = ai;
    }
}
__global__ void k_hfwd() {
    extern __shared__ float sm[];
    float* sr = sm; float* si = sm + 45*128;
    int c0 = blockIdx.x*128, kw = blockIdx.y, tid = threadIdx.x;
    for (int h = 0; h < 45; h++) {
        sr[h*128+tid] = g_Qr[(h*23+kw)*EE + c0+tid];
        si[h*128+tid] = g_Qi[(h*23+kw)*EE + c0+tid];
    }
    __syncthreads();
    for (int kh = 0; kh < 45; kh++) {
        float qr = 0.f, qi = 0.f;
        #pragma unroll 5
        for (int h = 0; h < 45; h++) {
            float ch = g_HC[kh*45+h], sh = g_HS[kh*45+h];
            float ur = sr[h*128+tid], ui = si[h*128+tid];
            qr += ur*ch + ui*sh;
            qi += ui*ch - ur*sh;
        }
        size_t row = (size_t)(kh*23+kw) * (2*EE);
        __half h2, l2;
        hsplit(qr, h2, l2); g_q2h[row + c0+tid] = h2;      g_q2l[row + c0+tid] = l2;
        hsplit(qi, h2, l2); g_q2h[row + EE + c0+tid] = h2; g_q2l[row + EE + c0+tid] = l2;
    }
}
__global__ void k_hinv2() {
    extern __shared__ float sm[];
    float* tr = sm; float* ti = sm + 45*128;
    int c0 = blockIdx.x*128, wp = blockIdx.y, tid = threadIdx.x;
    for (int hp = 0; hp < 45; hp++) {
        size_t row = (size_t)(hp*23+wp) * (2*EE);
        tr[hp*128+tid] = g_T[row + c0+tid]      + g_T[(size_t)NP*EE + row + c0+tid];
        ti[hp*128+tid] = g_T[row + EE + c0+tid] + g_T[(size_t)NP*EE + row + EE + c0+tid];
    }
    __syncthreads();
    for (int a = 0; a < 45; a++) {
        float zr = 0.f, zi = 0.f;
        #pragma unroll 5
        for (int hp = 0; hp < 45; hp++) {
            float ch = g_HC[a*45+hp], sh = g_HS[a*45+hp];
            float xr = tr[hp*128+tid], xi = ti[hp*128+tid];
            zr += xr*ch + xi*sh;
            zi += xi*ch - xr*sh;
        }
        g_Zr[(a*23+wp)*EE + c0+tid] = zr;
        g_Zi[(a*23+wp)*EE + c0+tid] = zi;
    }
}
__global__ void k_winv2(const float* __restrict__ nw, const float* __restrict__ nb) {
    extern __shared__ float sm[];
    float* zr = sm; float* zi = sm + 23*128;
    int c0 = blockIdx.x*128, a = blockIdx.y, tid = threadIdx.x;
    for (int wp = 0; wp < 23; wp++) {
        zr[wp*128+tid] = g_Zr[(a*23+wp)*EE + c0+tid];
        zi[wp*128+tid] = g_Zi[(a*23+wp)*EE + c0+tid];
    }
    __syncthreads();
    float wv = nw[c0+tid], bv = nb[c0+tid];
    for (int b = 0; b < 90; b++) {
        float y = 0.f;
        #pragma unroll
        for (int wp = 0; wp < 23; wp++) {
            y += zr[wp*128+tid]*g_WCm[b*90+wp] + zi[wp*128+tid]*g_WCp[b*90+wp];
        }
        int tok = a*90 + b;
        size_t idx = (size_t)tok*EE + c0+tid;
        float mu, ri;
        ln_from_sums(tok, mu, ri);
        float av = g_A[idx];
        float tv = (av - mu) * ri * wv + bv;
        g_A[idx] = av + y + tv;
    }
}

// ---------------- misc elementwise ----------------
__global__ void im2col_kernel(const float* __restrict__ x) {
    int idx = blockIdx.x*256 + threadIdx.x;
    if (idx >= NP*PKK) return;
    int p = idx / PKK, k = idx % PKK;
    int c = k >> 8, r = k & 255;
    int ph = r >> 4, pw = r & 15;
    int gh = p / 90, gw = p % 90;
    float v = x[(size_t)c*1036800 + (size_t)(gh*16+ph)*1440 + (gw*16+pw)];
    __half h, l; hsplit(v, h, l);
    size_t o = (size_t)p*PKK + k;
    g_pxh[o] = h; g_pxl[o] = l;
}

// ---------------- block-weight prep, ALL layers hoisted ----------------
__global__ void prep_pm_all(const float* __restrict__ w1, const float* __restrict__ w2) {
    int idx = blockIdx.x*256 + threadIdx.x;
    if (idx >= 12*BLK) return;
    int l = idx / BLK, i = idx % BLK;
    const float* w1l = w1 + (size_t)l*2*BLK;
    const float* w2l = w2 + (size_t)l*2*BLK;
    g_W1p[idx] = 0.5f*(w1l[i] + w1l[BLK+i]);
    g_W1m[idx] = 0.5f*(w1l[i] - w1l[BLK+i]);
    g_W2p[idx] = 0.5f*(w2l[i] + w2l[BLK+i]);
    g_W2m[idx] = 0.5f*(w2l[i] - w2l[BLK+i]);
}
__global__ void prep_ab_all() {
    int idx = blockIdx.x*128 + threadIdx.x;
    if (idx >= 12*BLK) return;
    int l = idx / BLK, rr = idx % BLK;
    int o = rr % 96;
    int i = (rr / 96) % 96;
    int b = rr / 9216;
    const float* P = g_W2p + (size_t)l*BLK + b*9216;
    const float* M = g_W2m + (size_t)l*BLK + b*9216;
    float aa = g_W2p[idx];
    float bb = g_W2m[idx] + g_W2p[idx];
    #pragma unroll 8
    for (int j = 0; j < 96; j++) {
        aa += P[i*96+j] * M[j*96+o];
        bb += M[i*96+j] * M[j*96+o];
    }
    g_W2a[idx] = aa;
    g_W2b[idx] = bb;
}
__global__ void prep_bs_all(const float* __restrict__ b2) {
    int idx = blockIdx.x*128 + threadIdx.x;
    if (idx >= 12*NBB*BSS) return;
    int l = idx / (NBB*BSS), rr = idx % (NBB*BSS);
    int o = rr % 96, b = rr / 96;
    const float* b2l = b2 + (size_t)l*2*NBB*BSS;
    float v = b2l[rr] + b2l[NBB*BSS + rr];
    const float* M = g_W2m + (size_t)l*BLK;
    #pragma unroll 8
    for (int j = 0; j < 96; j++) v += b2l[b*96+j] * M[(b*96+j)*96+o];
    g_bs[idx] = v;
}

// ---------------- fused block mixing (LN-gather + mix1 + mix2 + soft-thresh + split) ----------------
#define MROWS 45
#define MIXSM ((9216*2 + MROWS*96*2)*4)
__global__ void k_mixf(const float* __restrict__ b1l,
                       const float* __restrict__ nw, const float* __restrict__ nb,
                       int loff, int lbs) {
    extern __shared__ float sm[];
    float* sW1 = sm;
    float* sW2 = sm + 9216;
    float* sX  = sm + 18432;
    float* sY  = sX + MROWS*96;
    int b = blockIdx.x, tile = blockIdx.y;
    int t = threadIdx.x;
    int o = t % 96, rg = t / 96;
    for (int i = t; i < 9216; i += 288) {
        sW1[i] = g_W1p[loff + b*9216+i];
        sW2[i] = g_W1m[loff + b*9216+i];
    }
    int p0 = tile * MROWS;
    float nwv = nw[b*96+o], nbv = nb[b*96+o];
    for (int pp = rg; pp < MROWS; pp += 3) {
        int p = p0 + pp;
        int h = p / 23, w = p % 23;
        int shh = (45 - h) % 45;
        int sww = (90 - w) % 90;
        int tok = shh*90 + sww;
        float mu, ri;
        ln_from_sums(tok, mu, ri);
        float av = g_A[(size_t)tok*EE + b*96 + o];
        sX[pp*96+o] = g_a[(size_t)p*EE + b*96 + o] + g_a[(size_t)NFREQ*EE + (size_t)p*EE + b*96 + o];
        sY[pp*96+o] = (av - mu) * ri * nwv + nbv;
    }
    __syncthreads();
    float bk = b1l[b*96+o], bn = b1l[NBB*BSS + b*96+o];
    float ok_[15], on_[15];
    {
        int c = 0;
        for (int pp = rg; pp < MROWS; pp += 3, c++) {
            float ak = bk, an = bn;
            #pragma unroll 8
            for (int i = 0; i < 96; i++) {
                float xv = sX[pp*96+i], yv = sY[pp*96+i];
                float wp = sW1[i*96+o], wm = sW2[i*96+o];
                ak += xv*wp + yv*wm;
                an += yv*wp + xv*wm;
            }
            ok_[c] = fmaxf(ak, 0.f);
            on_[c] = fmaxf(an, 0.f);
        }
    }
    __syncthreads();
    {
        int c = 0;
        for (int pp = rg; pp < MROWS; pp += 3, c++) {
            sX[pp*96+o] = ok_[c];
            sY[pp*96+o] = on_[c];
        }
    }
    for (int i = t; i < 9216; i += 288) {
        sW1[i] = g_W2a[loff + b*9216+i];
        sW2[i] = g_W2b[loff + b*9216+i];
    }
    __syncthreads();
    float bsv = g_bs[lbs + b*96+o];
    for (int pp = rg; pp < MROWS; pp += 3) {
        float acc = bsv;
        #pragma unroll 8
        for (int i = 0; i < 96; i++) {
            acc += sX[pp*96+i]*sW1[i*96+o] + sY[pp*96+i]*sW2[i*96+o];
        }
        float aab = fabsf(acc) - 0.01f;
        float v = (aab > 0.f) ? copysignf(aab, acc) : 0.f;
        __half h, l; hsplit(v, h, l);
        size_t idx = (size_t)(p0+pp)*EE + b*96 + o;
        g_sh[idx] = h; g_sl[idx] = l;
    }
}

// ---------------- host orchestration ----------------
extern "C" void kernel_launch(void* const* d_in, const int* in_sizes, int n_in,
                              void* d_out, int out_size)
{
    const float* x        = (const float*)d_in[0];
    const float* patch_w  = (const float*)d_in[1];
    const float* patch_b  = (const float*)d_in[2];
    const float* pos      = (const float*)d_in[3];
    const float* norm1_w  = (const float*)d_in[4];
    const float* norm1_b  = (const float*)d_in[5];
    const float* w1       = (const float*)d_in[6];
    const float* b1       = (const float*)d_in[7];
    const float* w2       = (const float*)d_in[8];
    const float* b2       = (const float*)d_in[9];
    const float* norm2_w  = (const float*)d_in[10];
    const float* norm2_b  = (const float*)d_in[11];
    const float* fc1_w    = (const float*)d_in[12];
    const float* fc1_b    = (const float*)d_in[13];
    const float* fc2_w    = (const float*)d_in[14];
    const float* fc2_b    = (const float*)d_in[15];
    const float* head_w   = (const float*)d_in[16];
    float* out = (float*)d_out;

    float *pA,*pTT,*pa;
    cudaGetSymbolAddress((void**)&pA,  g_A);
    cudaGetSymbolAddress((void**)&pTT, g_T);
    cudaGetSymbolAddress((void**)&pa,  g_a);

    __half *pxh,*pxl,*th,*tl,*hbh,*hbl,*ah2,*al2,*q2h,*q2l,*sh,*sl;
    __half *pw,*fB,*iB,*f1,*f2,*hw;
    cudaGetSymbolAddress((void**)&pxh, g_pxh);  cudaGetSymbolAddress((void**)&pxl, g_pxl);
    cudaGetSymbolAddress((void**)&th,  g_th);   cudaGetSymbolAddress((void**)&tl,  g_tl);
    cudaGetSymbolAddress((void**)&hbh, g_hbh);  cudaGetSymbolAddress((void**)&hbl, g_hbl);
    cudaGetSymbolAddress((void**)&ah2, g_Ah2);  cudaGetSymbolAddress((void**)&al2, g_Al2);
    cudaGetSymbolAddress((void**)&q2h, g_q2h);  cudaGetSymbolAddress((void**)&q2l, g_q2l);
    cudaGetSymbolAddress((void**)&sh,  g_sh);   cudaGetSymbolAddress((void**)&sl,  g_sl);
    cudaGetSymbolAddress((void**)&pw,  g_pw);
    cudaGetSymbolAddress((void**)&fB,  g_fB);
    cudaGetSymbolAddress((void**)&iB,  g_iB);
    cudaGetSymbolAddress((void**)&f1,  g_f1);
    cudaGetSymbolAddress((void**)&f2,  g_f2);
    cudaGetSymbolAddress((void**)&hw,  g_hw);

    cudaFuncSetAttribute(k_wfwd,  cudaFuncAttributeMaxDynamicSharedMemorySize, 90*128*4 + 180*4);
    cudaFuncSetAttribute(k_hfwd,  cudaFuncAttributeMaxDynamicSharedMemorySize, 2*45*128*4);
    cudaFuncSetAttribute(k_hinv2, cudaFuncAttributeMaxDynamicSharedMemorySize, 2*45*128*4);
    cudaFuncSetAttribute(k_winv2, cudaFuncAttributeMaxDynamicSharedMemorySize, 2*23*128*4);
    cudaFuncSetAttribute(k_mixf,  cudaFuncAttributeMaxDynamicSharedMemorySize, MIXSM);
    const int SMB64  = 2*(2*A_TB + 64*SMSTR*2);    // 51200 (2-stage)
    const int SMB128 = 3*(2*A_TB + 128*SMSTR*2);   // 92160 (3-stage ring)
    cudaFuncSetAttribute((const void*)hgemm<0,64>,  cudaFuncAttributeMaxDynamicSharedMemorySize, SMB64);
    cudaFuncSetAttribute((const void*)hgemm<3,64>,  cudaFuncAttributeMaxDynamicSharedMemorySize, SMB64);
    cudaFuncSetAttribute((const void*)hgemm<4,64>,  cudaFuncAttributeMaxDynamicSharedMemorySize, SMB64);
    cudaFuncSetAttribute((const void*)hgemm<5,64>,  cudaFuncAttributeMaxDynamicSharedMemorySize, SMB64);
    cudaFuncSetAttribute((const void*)hgemm<2,128>, cudaFuncAttributeMaxDynamicSharedMemorySize, SMB128);
    cudaFuncSetAttribute((const void*)hgemm<6,128>, cudaFuncAttributeMaxDynamicSharedMemorySize, SMB128);

    // tables + weight converts + ALL-layer block-weight prep (once)
    tabC <<<(EE*EE + 255)/256, 256>>>();
    tab90<<<(GWw*GWw + 255)/256, 256>>>();
    tab45<<<(GHh*GHh + 255)/256, 256>>>();
    conv_kernel<<<(EE*PKK + 255)/256, 256>>>(patch_w, pw, EE*PKK);
    conv_kernel<<<(HDD*EE + 255)/256, 256>>>(head_w, hw, HDD*EE);
    conv_kernel<<<(12*HID*EE + 255)/256, 256>>>(fc1_w, f1, 12*HID*EE);
    conv_kernel<<<(12*EE*HID + 255)/256, 256>>>(fc2_w, f2, 12*EE*HID);
    prep_pm_all<<<(12*BLK + 255)/256, 256>>>(w1, w2);
    prep_ab_all<<<(12*BLK + 127)/128, 128>>>();
    prep_bs_all<<<(12*NBB*BSS + 127)/128, 128>>>(b2);

    const dim3 GB(256);

    // patch embed (bias + pos fused; emits LN1 stats for layer 0)
    im2col_kernel<<<(NP*PKK + 255)/256, 256>>>(x);
    hgemm<4,64><<<dim3(EE/64, MPAD/128), GB, SMB64>>>(pxh, pxl, pw, pA, nullptr, nullptr,
                                                      NP, EE, PKK, patch_b, pos, PKK, 0);

    for (int l = 0; l < 12; l++) {
        // ---- AFNO half ----
        k_wfwd<<<dim3(6, 45), 128, 90*128*4 + 180*4>>>(norm1_w + l*EE, norm1_b + l*EE);
        k_hfwd<<<dim3(6, 23), 128, 2*45*128*4>>>();
        // fwd C-stage GEMM: split-K2 (z=0: Q2r x (cos-sin); z=1: Q2i x (cos+sin))
        hgemm<0,64><<<dim3(EE/64, FPAD/128, 2), GB, SMB64>>>(q2h, q2l, fB, pa, nullptr, nullptr,
                                                             NFREQ, EE, EE, nullptr, nullptr,
                                                             2*EE, (long)NFREQ*EE);
        k_mixf<<<dim3(8, 23), 288, MIXSM>>>(b1 + (size_t)l*2*NBB*BSS,
                                            norm1_w + l*EE, norm1_b + l*EE, l*BLK, l*NBB*BSS);
        // inv C-stage GEMM: split-K2 over the 768 c-dimension
        hgemm<0,64><<<dim3((2*EE)/64, FPAD/128, 2), GB, SMB64>>>(sh, sl, iB, pTT, nullptr, nullptr,
                                                                 NFREQ, 2*EE, EE/2, nullptr, nullptr,
                                                                 EE, (long)NP*EE);
        k_hinv2<<<dim3(6, 23), 128, 2*45*128*4>>>();
        k_winv2<<<dim3(6, 45), 128, 2*23*128*4>>>(norm1_w + l*EE, norm1_b + l*EE);

        // ---- MLP half ----
        ln_h<<<NP, 256>>>(pA, th, tl, norm2_w + l*EE, norm2_b + l*EE);
        hgemm<2,128><<<dim3(HID/128, MPAD/128), GB, SMB128>>>(th, tl, f1 + (size_t)l*HID*EE,
                                                              nullptr, hbh, hbl, NP, HID, EE, fc1_b + l*HID, nullptr,
                                                              EE, 0);
        if (l < 11) {
            hgemm<3,64><<<dim3(EE/64, MPAD/128), GB, SMB64>>>(hbh, hbl, f2 + (size_t)l*EE*HID,
                                                              pA, nullptr, nullptr, NP, EE, HID, fc2_b + l*EE, nullptr,
                                                              HID, 0);
        } else {
            hgemm<5,64><<<dim3(EE/64, MPAD/128), GB, SMB64>>>(hbh, hbl, f2 + (size_t)l*EE*HID,
                                                              pA, ah2, al2, NP, EE, HID, fc2_b + l*EE, nullptr,
                                                              HID, 0);
        }
    }

    // head: GEMM scatters directly into the output image
    hgemm<6,128><<<dim3(HDD/128, MPAD/128), GB, SMB128>>>(ah2, al2, hw, out, nullptr, nullptr,
                                                          NP, HDD, EE, nullptr, nullptr, EE, 0);
}